// round 1
// baseline (speedup 1.0000x reference)
#include <cuda_runtime.h>
#include <cstdint>

// Problem constants
constexpr int cN  = 16;    // batch
constexpr int cL  = 256;   // tokens
constexpr int cS  = 128;   // collected sentence tokens
constexpr int cE  = 128;   // entities
constexpr int cA  = 9;     // args
constexpr int cD  = 768;   // embed dim
constexpr int cNH = 768;   // hidden
constexpr int cIDXW = cS + 2;   // 130
constexpr int cROLES = 24;      // ARG_ROLES+1
constexpr int KSPLIT_A = 6;

// ---------------- scratch (device globals; no allocation allowed) ----------
__device__ float g_sent  [cN * cS * cD];      // gathered sentence embeddings
__device__ float g_argraw[cN * cA * cD];      // gathered arg rows
__device__ float g_argemb[cN * cA * cD];      // arg_emb
__device__ float g_u2u   [cN * cA * cD];
__device__ float g_atok  [cN * cA * cD];      // arg_tokenAwared
__device__ float g_t2t   [cN * cS * cS];
__device__ float g_ent   [cN * cE * cD];      // entity_emb
__device__ float g_X     [cN * cE * cS];      // em^T @ t2t
__device__ float g_Ah2h  [cN * cE * cD];
__device__ float g_tok   [cN * cE * cD];      // token_argAwared
__device__ float g_w     [cN * cE * cA];
__device__ float g_Epart [cN * cE * cNH];
__device__ float g_Apart6[KSPLIT_A * cN * cA * cNH]; // split-K partials
__device__ float g_Apart [cN * cA * cNH];

// ---------------- packed fp32x2 FMA (Blackwell double-rate fp32) -----------
__device__ __forceinline__ void fma2(float2& d, float2 a, float2 b) {
    asm("fma.rn.f32x2 %0, %1, %2, %0;"
        : "+l"(reinterpret_cast<unsigned long long&>(d))
        : "l"(reinterpret_cast<unsigned long long&>(a)),
          "l"(reinterpret_cast<unsigned long long&>(b)));
}

// ---------------- gather sent_emb + arg_raw --------------------------------
__global__ void k_gather(const float* __restrict__ emb, const int* __restrict__ idxs) {
    int row = blockIdx.x;          // 0 .. N*(S+9)-1
    int tid = threadIdx.x;         // 192, float4 each
    if (row < cN * cS) {
        int n = row >> 7, s = row & 127;
        int src = idxs[n * cIDXW + s];
        const float4* sp = (const float4*)(emb + ((long)n * cL + src) * cD);
        ((float4*)(g_sent + (long)row * cD))[tid] = sp[tid];
    } else {
        int r = row - cN * cS;
        int n = r / cA, a = r % cA;
        int src = idxs[n * cIDXW + cS] + 1 + a;
        const float4* sp = (const float4*)(emb + ((long)n * cL + src) * cD);
        ((float4*)(g_argraw + (long)r * cD))[tid] = sp[tid];
    }
}

// ---------------- t2t: gather + head-mean + row-normalize + layer-avg ------
__global__ void k_t2t(const float* __restrict__ attn, const int* __restrict__ idxs) {
    int n = blockIdx.x >> 7, a = blockIdx.x & 127;
    int b = threadIdx.x;           // 128 threads
    __shared__ int   sc[cS];
    __shared__ float r0[cS], r1[cS], r2[cS];
    sc[b] = idxs[n * cIDXW + b];
    __syncthreads();
    int i = sc[a];
    int j = sc[b];
    const long lstride = (long)cN * 12 * cL * cL;
    long base = ((long)n * 12) * (cL * cL) + (long)i * cL + j;
    float a0 = 0.f, a1 = 0.f, a2 = 0.f;
#pragma unroll
    for (int h = 0; h < 12; ++h) {
        long o = base + (long)h * (cL * cL);
        a0 += __ldg(attn + o);
        a1 += __ldg(attn + o + lstride);
        a2 += __ldg(attn + o + 2 * lstride);
    }
    r0[b] = a0; r1[b] = a1; r2[b] = a2;
    __syncthreads();
    for (int st = 64; st > 0; st >>= 1) {
        if (b < st) { r0[b] += r0[b + st]; r1[b] += r1[b + st]; r2[b] += r2[b + st]; }
        __syncthreads();
    }
    float d0 = r0[0] * (1.f / 12.f) + 1e-9f;
    float d1 = r1[0] * (1.f / 12.f) + 1e-9f;
    float d2 = r2[0] * (1.f / 12.f) + 1e-9f;
    float val = ((a0 * (1.f / 12.f)) / d0 + (a1 * (1.f / 12.f)) / d1 +
                 (a2 * (1.f / 12.f)) / d2) * (1.f / 3.f);
    g_t2t[((long)(n * cS + a)) * cS + b] = val;
}

// ---------------- arg_emb, a2a softmax, u2u (tiny, one block per n) --------
__global__ void k_argsmall(const float* __restrict__ argw) {
    __shared__ float s_aw[cA * cA];
    __shared__ float s_ae[cA * cD];
    __shared__ float s_dot[cA * cA];
    __shared__ float s_a2a[cA * cA];
    int n = blockIdx.x, tid = threadIdx.x;   // 256 threads
    if (tid < cA * cA) s_aw[tid] = argw[n * cA * cA + tid];
    __syncthreads();
    for (int idx = tid; idx < cA * cD; idx += 256) {
        int a = idx / cD, d = idx % cD;
        float acc = 0.f;
#pragma unroll
        for (int k = 0; k < cA; ++k)
            acc += g_argraw[((long)(n * cA + k)) * cD + d] * s_aw[k * cA + a];
        s_ae[a * cD + d] = acc;
        g_argemb[((long)(n * cA + a)) * cD + d] = acc;
    }
    __syncthreads();
    int wa = tid >> 5, lane = tid & 31;
    for (int p = wa; p < cA * cA; p += 8) {
        int a = p / cA, b = p % cA;
        float acc = 0.f;
        for (int r = lane; r < cD; r += 32) acc += s_ae[a * cD + r] * s_ae[b * cD + r];
        for (int o = 16; o > 0; o >>= 1) acc += __shfl_xor_sync(0xffffffffu, acc, o);
        if (lane == 0) s_dot[p] = acc;
    }
    __syncthreads();
    if (tid < cA) {
        int a = tid;
        float mx = -1e30f;
        for (int b = 0; b < cA; ++b) mx = fmaxf(mx, s_dot[a * cA + b]);
        float e[cA], sum = 0.f;
        for (int b = 0; b < cA; ++b) { e[b] = expf(s_dot[a * cA + b] - mx); sum += e[b]; }
        float inv = 1.f / sum;
        for (int b = 0; b < cA; ++b) s_a2a[a * cA + b] = e[b] * inv;
    }
    __syncthreads();
    for (int idx = tid; idx < cA * cD; idx += 256) {
        int a = idx / cD, d = idx % cD;
        float acc = 0.f;
#pragma unroll
        for (int b = 0; b < cA; ++b) acc += s_a2a[a * cA + b] * s_ae[b * cD + d];
        g_u2u[((long)(n * cA + a)) * cD + d] = acc;
    }
}

// ---------------- generic 64x128 tile GEMM (fp32x2 inner) ------------------
// ROLE 0: ent  = em^T @ sent          (ATRANS, K=128)
// ROLE 1: X    = em^T @ t2t           (ATRANS, K=128, N=128)
// ROLE 2: Ah2h = X @ sent             (NN,     K=128)
// ROLE 3: Epart = ent@W0 + tok@W2 + Ah2h@W3   (NN, 3 chunks K=768)
// ROLE 4: Apart partials (split-K=6)  = argemb@W1 + atok@W4 + u2u@W5
template <int ROLE>
__global__ __launch_bounds__(256) void k_gemm(const float* __restrict__ PA,
                                              const float* __restrict__ PB) {
    constexpr bool ATRANS = (ROLE == 0 || ROLE == 1);
    constexpr int  NCH    = (ROLE >= 3) ? 3 : 1;
    constexpr int  KSPL   = (ROLE == 4) ? KSPLIT_A : 1;
    constexpr int  BK     = 16;

    const float *Ap0 = nullptr, *Ap1 = nullptr, *Ap2 = nullptr;
    const float *Bp0 = nullptr, *Bp1 = nullptr, *Bp2 = nullptr;
    float* Cp = nullptr;
    long aStr = 0, bStr = 0, cStr = 0;
    int ldA = 0, ldB = 0, ldC = 0, M = 0, Kc = 0;

    if (ROLE == 0) { Ap0 = PA;      aStr = cS * cE; ldA = cE;
                     Bp0 = g_sent;  bStr = cS * cD; ldB = cD;
                     Cp = g_ent;    cStr = cE * cD; ldC = cD; M = cE; Kc = cS; }
    if (ROLE == 1) { Ap0 = PA;      aStr = cS * cE; ldA = cE;
                     Bp0 = g_t2t;   bStr = cS * cS; ldB = cS;
                     Cp = g_X;      cStr = cE * cS; ldC = cS; M = cE; Kc = cS; }
    if (ROLE == 2) { Ap0 = g_X;     aStr = cE * cS; ldA = cS;
                     Bp0 = g_sent;  bStr = cS * cD; ldB = cD;
                     Cp = g_Ah2h;   cStr = cE * cD; ldC = cD; M = cE; Kc = cS; }
    if (ROLE == 3) { Ap0 = g_ent; Ap1 = g_tok; Ap2 = g_Ah2h; aStr = cE * cD; ldA = cD;
                     Bp0 = PB; Bp1 = PB + 2L * cD * cNH; Bp2 = PB + 3L * cD * cNH;
                     bStr = 0; ldB = cNH;
                     Cp = g_Epart;  cStr = cE * cNH; ldC = cNH; M = cE; Kc = cD; }
    if (ROLE == 4) { Ap0 = g_argemb; Ap1 = g_atok; Ap2 = g_u2u; aStr = 0; ldA = cD;
                     Bp0 = PB + 1L * cD * cNH; Bp1 = PB + 4L * cD * cNH;
                     Bp2 = PB + 5L * cD * cNH; bStr = 0; ldB = cNH;
                     Cp = g_Apart6; cStr = 0; ldC = cNH; M = cN * cA; Kc = cD; }

    const float* Ap[3] = {Ap0, Ap1, Ap2};
    const float* Bp[3] = {Bp0, Bp1, Bp2};

    __shared__ float As[BK][68];
    __shared__ float Bs[BK][128];

    int z  = blockIdx.z;
    int n  = z / KSPL;
    int ks = z % KSPL;
    int m0 = blockIdx.x * 64;
    int n0 = blockIdx.y * 128;
    int tid = threadIdx.x;
    int tx = tid & 15, ty = tid >> 4;

    if (ROLE == 4) Cp += (long)ks * (cN * cA * cNH);  // private split-K slice

    float2 acc[4][4];
#pragma unroll
    for (int i = 0; i < 4; ++i)
#pragma unroll
        for (int p = 0; p < 4; ++p) acc[i][p] = make_float2(0.f, 0.f);

    int chB = 0, chE = NCH, koB = 0, koE = Kc;
    if (KSPL > 1) {
        constexpr int spc = KSPL / NCH;     // 2
        chB = ks / spc; chE = chB + 1;
        int len = Kc / spc;
        koB = (ks % spc) * len; koE = koB + len;
    }

    for (int ch = chB; ch < chE; ++ch) {
        const float* A = Ap[ch] + (long)n * aStr;
        const float* B = Bp[ch] + (long)n * bStr;
        for (int ko = koB; ko < koE; ko += BK) {
            if (ATRANS) {
                int r = tid >> 4, c4 = (tid & 15) << 2;
                float4 v = *(const float4*)(A + (long)(ko + r) * ldA + m0 + c4);
                As[r][c4 + 0] = v.x; As[r][c4 + 1] = v.y;
                As[r][c4 + 2] = v.z; As[r][c4 + 3] = v.w;
            } else {
                int m = tid >> 2, kq = (tid & 3) << 2;
                float4 v = make_float4(0.f, 0.f, 0.f, 0.f);
                if (m0 + m < M) v = *(const float4*)(A + (long)(m0 + m) * ldA + ko + kq);
                As[kq + 0][m] = v.x; As[kq + 1][m] = v.y;
                As[kq + 2][m] = v.z; As[kq + 3][m] = v.w;
            }
            {
                int r = tid >> 5, c4 = (tid & 31) << 2;
#pragma unroll
                for (int rr = 0; rr < 2; ++rr) {
                    float4 v = *(const float4*)(B + (long)(ko + r + rr * 8) * ldB + n0 + c4);
                    *(float4*)&Bs[r + rr * 8][c4] = v;
                }
            }
            __syncthreads();
#pragma unroll
            for (int kk = 0; kk < BK; ++kk) {
                float4 av = *(const float4*)&As[kk][ty << 2];
                float a_[4] = {av.x, av.y, av.z, av.w};
                float2 b_[4];
#pragma unroll
                for (int p = 0; p < 4; ++p)
                    b_[p] = *(const float2*)&Bs[kk][(tx << 1) + (p << 5)];
#pragma unroll
                for (int i = 0; i < 4; ++i) {
                    float2 ad = make_float2(a_[i], a_[i]);
#pragma unroll
                    for (int p = 0; p < 4; ++p) fma2(acc[i][p], ad, b_[p]);
                }
            }
            __syncthreads();
        }
    }

    float* Cn = Cp + (long)n * cStr;
#pragma unroll
    for (int i = 0; i < 4; ++i) {
        int m = m0 + (ty << 2) + i;
        if (m < M) {
#pragma unroll
            for (int p = 0; p < 4; ++p) {
                int col = n0 + (tx << 1) + (p << 5);
                *(float2*)&Cn[(long)m * ldC + col] = acc[i][p];
            }
        }
    }
}

// ---------------- w = (ent . argemb / sqrt(D) - 5)/2 -----------------------
__global__ void k_w() {
    int n = blockIdx.x >> 7, e = blockIdx.x & 127;
    int wa = threadIdx.x >> 5, lane = threadIdx.x & 31;   // 9 warps
    const float* er = g_ent + ((long)(n * cE + e)) * cD;
    const float* ar = g_argemb + ((long)(n * cA + wa)) * cD;
    float acc = 0.f;
    for (int r = lane; r < cD; r += 32) acc += er[r] * ar[r];
    for (int o = 16; o > 0; o >>= 1) acc += __shfl_xor_sync(0xffffffffu, acc, o);
    if (lane == 0)
        g_w[(n * cE + e) * cA + wa] = (acc * 0.03608439182435161f - 5.0f) * 0.5f;
}

// ---------------- token_argAwared[n,e,:] = sum_a w * argemb ---------------
__global__ void k_tok() {
    int n = blockIdx.x >> 7, e = blockIdx.x & 127;
    __shared__ float sw[cA];
    if (threadIdx.x < cA) sw[threadIdx.x] = g_w[(n * cE + e) * cA + threadIdx.x];
    __syncthreads();
    int d = threadIdx.x << 2;   // 192 threads * float4
    float4 acc = make_float4(0.f, 0.f, 0.f, 0.f);
#pragma unroll
    for (int a = 0; a < cA; ++a) {
        float4 v = *(const float4*)&g_argemb[((long)(n * cA + a)) * cD + d];
        float wv = sw[a];
        acc.x += wv * v.x; acc.y += wv * v.y; acc.z += wv * v.z; acc.w += wv * v.w;
    }
    *(float4*)&g_tok[((long)(n * cE + e)) * cD + d] = acc;
}

// ---------------- arg_tokenAwared[n,a,:] = sum_e w * ent -------------------
__global__ void k_atok() {
    int n = blockIdx.x / cA, a = blockIdx.x % cA;
    int d = threadIdx.x << 2;   // 192 threads
    float4 acc = make_float4(0.f, 0.f, 0.f, 0.f);
    for (int e = 0; e < cE; ++e) {
        float wv = g_w[(n * cE + e) * cA + a];
        float4 v = *(const float4*)&g_ent[((long)(n * cE + e)) * cD + d];
        acc.x += wv * v.x; acc.y += wv * v.y; acc.z += wv * v.z; acc.w += wv * v.w;
    }
    *(float4*)&g_atok[((long)(n * cA + a)) * cD + d] = acc;
}

// ---------------- reduce split-K Apart partials ----------------------------
__global__ void k_redA() {
    int i = blockIdx.x * 256 + threadIdx.x;
    if (i < cN * cA * cNH) {
        float s = 0.f;
#pragma unroll
        for (int k = 0; k < KSPLIT_A; ++k) s += g_Apart6[(long)k * cN * cA * cNH + i];
        g_Apart[i] = s;
    }
}

// ---------------- epilogue: gelu, score, scatter ---------------------------
__global__ void k_final(const float* __restrict__ b1, const float* __restrict__ W2,
                        const float* __restrict__ b2, const int* __restrict__ argmap,
                        float* __restrict__ out) {
    int n = blockIdx.x >> 7, e = blockIdx.x & 127;
    __shared__ float sEp[cNH];
    __shared__ float sScore[cA];
    int tid = threadIdx.x;   // 288 = 9 warps
    for (int i = tid; i < cNH; i += 288)
        sEp[i] = g_Epart[((long)(n * cE + e)) * cNH + i];
    __syncthreads();
    int wa = tid >> 5, lane = tid & 31;
    {
        const float* ap = g_Apart + ((long)(n * cA + wa)) * cNH;
        float acc = 0.f;
        for (int r = lane; r < cNH; r += 32) {
            float pre = sEp[r] + ap[r] + b1[r];
            float h = 0.5f * pre * (1.0f + erff(pre * 0.7071067811865476f));
            acc += h * W2[r];
        }
        for (int o = 16; o > 0; o >>= 1) acc += __shfl_xor_sync(0xffffffffu, acc, o);
        if (lane == 0) sScore[wa] = acc + b2[0];
    }
    __syncthreads();
    if (tid < cROLES) {
        float v = -1000000.0f;
#pragma unroll
        for (int a = 0; a < cA; ++a)
            if (argmap[n * cA + a] == tid) v = sScore[a];
        out[((long)(n * cE + e)) * cROLES + tid] = v;
    }
}

// ---------------- launch ---------------------------------------------------
extern "C" void kernel_launch(void* const* d_in, const int* in_sizes, int n_in,
                              void* d_out, int out_size) {
    const float* emb   = (const float*)d_in[0];   // all_embeddings (N,L,D)
    const float* attn  = (const float*)d_in[1];   // attn_last3 (3,N,12,L,L)
    const float* em    = (const float*)d_in[2];   // entity_mapping (N,S,E)
    const float* argw  = (const float*)d_in[3];   // arg_weight_matrices (N,9,9)
    // d_in[4] = is_triggers (dead code in reference)
    const float* W1    = (const float*)d_in[5];   // (4608,768)
    const float* b1    = (const float*)d_in[6];
    const float* W2    = (const float*)d_in[7];
    const float* b2    = (const float*)d_in[8];
    const int*   idxs  = (const int*)d_in[9];     // (N,130)
    const int*   amap  = (const int*)d_in[10];    // (N,9)
    float* out = (float*)d_out;

    k_gather  <<<cN * (cS + cA), 192>>>(emb, idxs);
    k_t2t     <<<cN * cS, 128>>>(attn, idxs);
    k_argsmall<<<cN, 256>>>(argw);
    k_gemm<0> <<<dim3(2, 6, cN), 256>>>(em, nullptr);      // entity_emb
    k_gemm<1> <<<dim3(2, 1, cN), 256>>>(em, nullptr);      // X = em^T @ t2t
    k_gemm<2> <<<dim3(2, 6, cN), 256>>>(nullptr, nullptr); // Ah2h = X @ sent
    k_w       <<<cN * cE, 288>>>();
    k_tok     <<<cN * cE, 192>>>();
    k_atok    <<<cN * cA, 192>>>();
    k_gemm<3> <<<dim3(2, 6, cN), 256>>>(nullptr, W1);      // Epart (big GEMM)
    k_gemm<4> <<<dim3(3, 6, KSPLIT_A), 256>>>(nullptr, W1);// Apart partials
    k_redA    <<<(cN * cA * cNH + 255) / 256, 256>>>();
    k_final   <<<cN * cE, 288>>>(b1, W2, b2, amap, out);
}

// round 2
// speedup vs baseline: 1.0065x; 1.0065x over previous
#include <cuda_runtime.h>
#include <cstdint>

// Problem constants
constexpr int cN  = 16;    // batch
constexpr int cL  = 256;   // tokens
constexpr int cS  = 128;   // collected sentence tokens
constexpr int cE  = 128;   // entities
constexpr int cA  = 9;     // args
constexpr int cD  = 768;   // embed dim
constexpr int cNH = 768;   // hidden
constexpr int cIDXW = cS + 2;   // 130
constexpr int cROLES = 24;      // ARG_ROLES+1
constexpr int KSPLIT_A = 6;

// ---------------- scratch (device globals; no allocation allowed) ----------
__device__ float g_sent  [cN * cS * cD];      // gathered sentence embeddings
__device__ float g_argraw[cN * cA * cD];      // gathered arg rows
__device__ float g_argemb[cN * cA * cD];      // arg_emb
__device__ float g_u2u   [cN * cA * cD];
__device__ float g_atok  [cN * cA * cD];      // arg_tokenAwared
__device__ float g_t2t   [cN * cS * cS];
__device__ float g_ent   [cN * cE * cD];      // entity_emb
__device__ float g_X     [cN * cE * cS];      // em^T @ t2t
__device__ float g_Ah2h  [cN * cE * cD];
__device__ float g_tok   [cN * cE * cD];      // token_argAwared
__device__ float g_w     [cN * cE * cA];
__device__ float g_Epart [cN * cE * cNH];
__device__ float g_Apart6[KSPLIT_A * cN * cA * cNH]; // split-K partials
__device__ float g_Apart [cN * cA * cNH];

// ---------------- packed fp32x2 FMA (Blackwell double-rate fp32) -----------
__device__ __forceinline__ void fma2(float2& d, float2 a, float2 b) {
    asm("fma.rn.f32x2 %0, %1, %2, %0;"
        : "+l"(reinterpret_cast<unsigned long long&>(d))
        : "l"(reinterpret_cast<unsigned long long&>(a)),
          "l"(reinterpret_cast<unsigned long long&>(b)));
}

// ---------------- gather sent_emb + arg_raw --------------------------------
__global__ void k_gather(const float* __restrict__ emb, const int* __restrict__ idxs) {
    int row = blockIdx.x;          // 0 .. N*(S+9)-1
    int tid = threadIdx.x;         // 192, float4 each
    if (row < cN * cS) {
        int n = row >> 7, s = row & 127;
        int src = idxs[n * cIDXW + s];
        const float4* sp = (const float4*)(emb + ((long)n * cL + src) * cD);
        ((float4*)(g_sent + (long)row * cD))[tid] = sp[tid];
    } else {
        int r = row - cN * cS;
        int n = r / cA, a = r % cA;
        int src = idxs[n * cIDXW + cS] + 1 + a;
        const float4* sp = (const float4*)(emb + ((long)n * cL + src) * cD);
        ((float4*)(g_argraw + (long)r * cD))[tid] = sp[tid];
    }
}

// ---------------- t2t: gather + head-mean + row-normalize + layer-avg ------
__global__ void k_t2t(const float* __restrict__ attn, const int* __restrict__ idxs) {
    int n = blockIdx.x >> 7, a = blockIdx.x & 127;
    int b = threadIdx.x;           // 128 threads
    __shared__ int   sc[cS];
    __shared__ float r0[cS], r1[cS], r2[cS];
    sc[b] = idxs[n * cIDXW + b];
    __syncthreads();
    int i = sc[a];
    int j = sc[b];
    const long lstride = (long)cN * 12 * cL * cL;
    long base = ((long)n * 12) * (cL * cL) + (long)i * cL + j;
    float a0 = 0.f, a1 = 0.f, a2 = 0.f;
#pragma unroll
    for (int h = 0; h < 12; ++h) {
        long o = base + (long)h * (cL * cL);
        a0 += __ldg(attn + o);
        a1 += __ldg(attn + o + lstride);
        a2 += __ldg(attn + o + 2 * lstride);
    }
    r0[b] = a0; r1[b] = a1; r2[b] = a2;
    __syncthreads();
    for (int st = 64; st > 0; st >>= 1) {
        if (b < st) { r0[b] += r0[b + st]; r1[b] += r1[b + st]; r2[b] += r2[b + st]; }
        __syncthreads();
    }
    float d0 = r0[0] * (1.f / 12.f) + 1e-9f;
    float d1 = r1[0] * (1.f / 12.f) + 1e-9f;
    float d2 = r2[0] * (1.f / 12.f) + 1e-9f;
    float val = ((a0 * (1.f / 12.f)) / d0 + (a1 * (1.f / 12.f)) / d1 +
                 (a2 * (1.f / 12.f)) / d2) * (1.f / 3.f);
    g_t2t[((long)(n * cS + a)) * cS + b] = val;
}

// ---------------- arg_emb, a2a softmax, u2u (tiny, one block per n) --------
__global__ void k_argsmall(const float* __restrict__ argw) {
    __shared__ float s_aw[cA * cA];
    __shared__ float s_ae[cA * cD];
    __shared__ float s_dot[cA * cA];
    __shared__ float s_a2a[cA * cA];
    int n = blockIdx.x, tid = threadIdx.x;   // 256 threads
    if (tid < cA * cA) s_aw[tid] = argw[n * cA * cA + tid];
    __syncthreads();
    for (int idx = tid; idx < cA * cD; idx += 256) {
        int a = idx / cD, d = idx % cD;
        float acc = 0.f;
#pragma unroll
        for (int k = 0; k < cA; ++k)
            acc += g_argraw[((long)(n * cA + k)) * cD + d] * s_aw[k * cA + a];
        s_ae[a * cD + d] = acc;
        g_argemb[((long)(n * cA + a)) * cD + d] = acc;
    }
    __syncthreads();
    int wa = tid >> 5, lane = tid & 31;
    for (int p = wa; p < cA * cA; p += 8) {
        int a = p / cA, b = p % cA;
        float acc = 0.f;
        for (int r = lane; r < cD; r += 32) acc += s_ae[a * cD + r] * s_ae[b * cD + r];
        for (int o = 16; o > 0; o >>= 1) acc += __shfl_xor_sync(0xffffffffu, acc, o);
        if (lane == 0) s_dot[p] = acc;
    }
    __syncthreads();
    if (tid < cA) {
        int a = tid;
        float mx = -1e30f;
        for (int b = 0; b < cA; ++b) mx = fmaxf(mx, s_dot[a * cA + b]);
        float e[cA], sum = 0.f;
        for (int b = 0; b < cA; ++b) { e[b] = expf(s_dot[a * cA + b] - mx); sum += e[b]; }
        float inv = 1.f / sum;
        for (int b = 0; b < cA; ++b) s_a2a[a * cA + b] = e[b] * inv;
    }
    __syncthreads();
    for (int idx = tid; idx < cA * cD; idx += 256) {
        int a = idx / cD, d = idx % cD;
        float acc = 0.f;
#pragma unroll
        for (int b = 0; b < cA; ++b) acc += s_a2a[a * cA + b] * s_ae[b * cD + d];
        g_u2u[((long)(n * cA + a)) * cD + d] = acc;
    }
}

// ---------------- generic 64x128 tile GEMM (fp32x2 inner) ------------------
// ROLE 0: ent  = em^T @ sent          (ATRANS, K=128)
// ROLE 1: X    = em^T @ t2t           (ATRANS, K=128, N=128)
// ROLE 2: Ah2h = X @ sent             (NN,     K=128)
// ROLE 3: Epart = ent@W0 + tok@W2 + Ah2h@W3   (NN, 3 chunks K=768)
// ROLE 4: Apart partials (split-K=6)  = argemb@W1 + atok@W4 + u2u@W5
template <int ROLE>
__global__ __launch_bounds__(256) void k_gemm(const float* __restrict__ PA,
                                              const float* __restrict__ PB) {
    constexpr bool ATRANS = (ROLE == 0 || ROLE == 1);
    constexpr int  NCH    = (ROLE >= 3) ? 3 : 1;
    constexpr int  KSPL   = (ROLE == 4) ? KSPLIT_A : 1;
    constexpr int  BK     = 16;

    const float *Ap0 = nullptr, *Ap1 = nullptr, *Ap2 = nullptr;
    const float *Bp0 = nullptr, *Bp1 = nullptr, *Bp2 = nullptr;
    float* Cp = nullptr;
    long aStr = 0, bStr = 0, cStr = 0;
    int ldA = 0, ldB = 0, ldC = 0, M = 0, Kc = 0;

    if (ROLE == 0) { Ap0 = PA;      aStr = cS * cE; ldA = cE;
                     Bp0 = g_sent;  bStr = cS * cD; ldB = cD;
                     Cp = g_ent;    cStr = cE * cD; ldC = cD; M = cE; Kc = cS; }
    if (ROLE == 1) { Ap0 = PA;      aStr = cS * cE; ldA = cE;
                     Bp0 = g_t2t;   bStr = cS * cS; ldB = cS;
                     Cp = g_X;      cStr = cE * cS; ldC = cS; M = cE; Kc = cS; }
    if (ROLE == 2) { Ap0 = g_X;     aStr = cE * cS; ldA = cS;
                     Bp0 = g_sent;  bStr = cS * cD; ldB = cD;
                     Cp = g_Ah2h;   cStr = cE * cD; ldC = cD; M = cE; Kc = cS; }
    if (ROLE == 3) { Ap0 = g_ent; Ap1 = g_tok; Ap2 = g_Ah2h; aStr = cE * cD; ldA = cD;
                     Bp0 = PB; Bp1 = PB + 2L * cD * cNH; Bp2 = PB + 3L * cD * cNH;
                     bStr = 0; ldB = cNH;
                     Cp = g_Epart;  cStr = cE * cNH; ldC = cNH; M = cE; Kc = cD; }
    if (ROLE == 4) { Ap0 = g_argemb; Ap1 = g_atok; Ap2 = g_u2u; aStr = 0; ldA = cD;
                     Bp0 = PB + 1L * cD * cNH; Bp1 = PB + 4L * cD * cNH;
                     Bp2 = PB + 5L * cD * cNH; bStr = 0; ldB = cNH;
                     Cp = g_Apart6; cStr = 0; ldC = cNH; M = cN * cA; Kc = cD; }

    const float* Ap[3] = {Ap0, Ap1, Ap2};
    const float* Bp[3] = {Bp0, Bp1, Bp2};

    __shared__ float As[BK][68];
    __shared__ float Bs[BK][128];

    int z  = blockIdx.z;
    int n  = z / KSPL;
    int ks = z % KSPL;
    int m0 = blockIdx.x * 64;
    int n0 = blockIdx.y * 128;
    int tid = threadIdx.x;
    int tx = tid & 15, ty = tid >> 4;

    if (ROLE == 4) Cp += (long)ks * (cN * cA * cNH);  // private split-K slice

    float2 acc[4][4];
#pragma unroll
    for (int i = 0; i < 4; ++i)
#pragma unroll
        for (int p = 0; p < 4; ++p) acc[i][p] = make_float2(0.f, 0.f);

    int chB = 0, chE = NCH, koB = 0, koE = Kc;
    if (KSPL > 1) {
        constexpr int spc = KSPL / NCH;     // 2
        chB = ks / spc; chE = chB + 1;
        int len = Kc / spc;
        koB = (ks % spc) * len; koE = koB + len;
    }

    for (int ch = chB; ch < chE; ++ch) {
        const float* A = Ap[ch] + (long)n * aStr;
        const float* B = Bp[ch] + (long)n * bStr;
        for (int ko = koB; ko < koE; ko += BK) {
            if (ATRANS) {
                int r = tid >> 4, c4 = (tid & 15) << 2;
                float4 v = *(const float4*)(A + (long)(ko + r) * ldA + m0 + c4);
                As[r][c4 + 0] = v.x; As[r][c4 + 1] = v.y;
                As[r][c4 + 2] = v.z; As[r][c4 + 3] = v.w;
            } else {
                int m = tid >> 2, kq = (tid & 3) << 2;
                float4 v = make_float4(0.f, 0.f, 0.f, 0.f);
                if (m0 + m < M) v = *(const float4*)(A + (long)(m0 + m) * ldA + ko + kq);
                As[kq + 0][m] = v.x; As[kq + 1][m] = v.y;
                As[kq + 2][m] = v.z; As[kq + 3][m] = v.w;
            }
            {
                int r = tid >> 5, c4 = (tid & 31) << 2;
#pragma unroll
                for (int rr = 0; rr < 2; ++rr) {
                    float4 v = *(const float4*)(B + (long)(ko + r + rr * 8) * ldB + n0 + c4);
                    *(float4*)&Bs[r + rr * 8][c4] = v;
                }
            }
            __syncthreads();
#pragma unroll
            for (int kk = 0; kk < BK; ++kk) {
                float4 av = *(const float4*)&As[kk][ty << 2];
                float a_[4] = {av.x, av.y, av.z, av.w};
                float2 b_[4];
#pragma unroll
                for (int p = 0; p < 4; ++p)
                    b_[p] = *(const float2*)&Bs[kk][(tx << 1) + (p << 5)];
#pragma unroll
                for (int i = 0; i < 4; ++i) {
                    float2 ad = make_float2(a_[i], a_[i]);
#pragma unroll
                    for (int p = 0; p < 4; ++p) fma2(acc[i][p], ad, b_[p]);
                }
            }
            __syncthreads();
        }
    }

    float* Cn = Cp + (long)n * cStr;
#pragma unroll
    for (int i = 0; i < 4; ++i) {
        int m = m0 + (ty << 2) + i;
        if (m < M) {
#pragma unroll
            for (int p = 0; p < 4; ++p) {
                int col = n0 + (tx << 1) + (p << 5);
                *(float2*)&Cn[(long)m * ldC + col] = acc[i][p];
            }
        }
    }
}

// ---------------- w = (ent . argemb / sqrt(D) - 5)/2 -----------------------
__global__ void k_w() {
    int n = blockIdx.x >> 7, e = blockIdx.x & 127;
    int wa = threadIdx.x >> 5, lane = threadIdx.x & 31;   // 9 warps
    const float* er = g_ent + ((long)(n * cE + e)) * cD;
    const float* ar = g_argemb + ((long)(n * cA + wa)) * cD;
    float acc = 0.f;
    for (int r = lane; r < cD; r += 32) acc += er[r] * ar[r];
    for (int o = 16; o > 0; o >>= 1) acc += __shfl_xor_sync(0xffffffffu, acc, o);
    if (lane == 0)
        g_w[(n * cE + e) * cA + wa] = (acc * 0.03608439182435161f - 5.0f) * 0.5f;
}

// ---------------- token_argAwared[n,e,:] = sum_a w * argemb ---------------
__global__ void k_tok() {
    int n = blockIdx.x >> 7, e = blockIdx.x & 127;
    __shared__ float sw[cA];
    if (threadIdx.x < cA) sw[threadIdx.x] = g_w[(n * cE + e) * cA + threadIdx.x];
    __syncthreads();
    int d = threadIdx.x << 2;   // 192 threads * float4
    float4 acc = make_float4(0.f, 0.f, 0.f, 0.f);
#pragma unroll
    for (int a = 0; a < cA; ++a) {
        float4 v = *(const float4*)&g_argemb[((long)(n * cA + a)) * cD + d];
        float wv = sw[a];
        acc.x += wv * v.x; acc.y += wv * v.y; acc.z += wv * v.z; acc.w += wv * v.w;
    }
    *(float4*)&g_tok[((long)(n * cE + e)) * cD + d] = acc;
}

// ---------------- arg_tokenAwared[n,a,:] = sum_e w * ent -------------------
__global__ void k_atok() {
    int n = blockIdx.x / cA, a = blockIdx.x % cA;
    int d = threadIdx.x << 2;   // 192 threads
    float4 acc = make_float4(0.f, 0.f, 0.f, 0.f);
    for (int e = 0; e < cE; ++e) {
        float wv = g_w[(n * cE + e) * cA + a];
        float4 v = *(const float4*)&g_ent[((long)(n * cE + e)) * cD + d];
        acc.x += wv * v.x; acc.y += wv * v.y; acc.z += wv * v.z; acc.w += wv * v.w;
    }
    *(float4*)&g_atok[((long)(n * cA + a)) * cD + d] = acc;
}

// ---------------- reduce split-K Apart partials ----------------------------
__global__ void k_redA() {
    int i = blockIdx.x * 256 + threadIdx.x;
    if (i < cN * cA * cNH) {
        float s = 0.f;
#pragma unroll
        for (int k = 0; k < KSPLIT_A; ++k) s += g_Apart6[(long)k * cN * cA * cNH + i];
        g_Apart[i] = s;
    }
}

// ---------------- epilogue: gelu, score, scatter ---------------------------
__global__ void k_final(const float* __restrict__ b1, const float* __restrict__ W2,
                        const float* __restrict__ b2, const int* __restrict__ argmap,
                        float* __restrict__ out) {
    int n = blockIdx.x >> 7, e = blockIdx.x & 127;
    __shared__ float sEp[cNH];
    __shared__ float sScore[cA];
    int tid = threadIdx.x;   // 288 = 9 warps
    for (int i = tid; i < cNH; i += 288)
        sEp[i] = g_Epart[((long)(n * cE + e)) * cNH + i];
    __syncthreads();
    int wa = tid >> 5, lane = tid & 31;
    {
        const float* ap = g_Apart + ((long)(n * cA + wa)) * cNH;
        float acc = 0.f;
        for (int r = lane; r < cNH; r += 32) {
            float pre = sEp[r] + ap[r] + b1[r];
            float h = 0.5f * pre * (1.0f + erff(pre * 0.7071067811865476f));
            acc += h * W2[r];
        }
        for (int o = 16; o > 0; o >>= 1) acc += __shfl_xor_sync(0xffffffffu, acc, o);
        if (lane == 0) sScore[wa] = acc + b2[0];
    }
    __syncthreads();
    if (tid < cROLES) {
        float v = -1000000.0f;
#pragma unroll
        for (int a = 0; a < cA; ++a)
            if (argmap[n * cA + a] == tid) v = sScore[a];
        out[((long)(n * cE + e)) * cROLES + tid] = v;
    }
}

// ---------------- launch ---------------------------------------------------
extern "C" void kernel_launch(void* const* d_in, const int* in_sizes, int n_in,
                              void* d_out, int out_size) {
    const float* emb   = (const float*)d_in[0];   // all_embeddings (N,L,D)
    const float* attn  = (const float*)d_in[1];   // attn_last3 (3,N,12,L,L)
    const float* em    = (const float*)d_in[2];   // entity_mapping (N,S,E)
    const float* argw  = (const float*)d_in[3];   // arg_weight_matrices (N,9,9)
    // d_in[4] = is_triggers (dead code in reference)
    const float* W1    = (const float*)d_in[5];   // (4608,768)
    const float* b1    = (const float*)d_in[6];
    const float* W2    = (const float*)d_in[7];
    const float* b2    = (const float*)d_in[8];
    const int*   idxs  = (const int*)d_in[9];     // (N,130)
    const int*   amap  = (const int*)d_in[10];    // (N,9)
    float* out = (float*)d_out;

    k_gather  <<<cN * (cS + cA), 192>>>(emb, idxs);
    k_t2t     <<<cN * cS, 128>>>(attn, idxs);
    k_argsmall<<<cN, 256>>>(argw);
    k_gemm<0> <<<dim3(2, 6, cN), 256>>>(em, nullptr);      // entity_emb
    k_gemm<1> <<<dim3(2, 1, cN), 256>>>(em, nullptr);      // X = em^T @ t2t
    k_gemm<2> <<<dim3(2, 6, cN), 256>>>(nullptr, nullptr); // Ah2h = X @ sent
    k_w       <<<cN * cE, 288>>>();
    k_tok     <<<cN * cE, 192>>>();
    k_atok    <<<cN * cA, 192>>>();
    k_gemm<3> <<<dim3(2, 6, cN), 256>>>(nullptr, W1);      // Epart (big GEMM)
    k_gemm<4> <<<dim3(3, 6, KSPLIT_A), 256>>>(nullptr, W1);// Apart partials
    k_redA    <<<(cN * cA * cNH + 255) / 256, 256>>>();
    k_final   <<<cN * cE, 288>>>(b1, W2, b2, amap, out);
}

// round 4
// speedup vs baseline: 1.8843x; 1.8720x over previous
#include <cuda_runtime.h>
#include <cuda_bf16.h>
#include <cstdint>

constexpr int cN  = 16, cL = 256, cS = 128, cE = 128, cA = 9;
constexpr int cD  = 768, cNH = 768, cIDXW = 130, cROLES = 24;
constexpr int KSPLIT_A = 6;

// ---------------- scratch ---------------------------------------------------
__device__ float g_sent  [cN * cS * cD];
__device__ float g_argraw[cN * cA * cD];
__device__ float g_argemb[cN * cA * cD];
__device__ float g_u2u   [cN * cA * cD];
__device__ float g_atok  [cN * cA * cD];
__device__ float g_t2t   [cN * cS * cS];
__device__ float g_ent   [cN * cE * cD];
__device__ float g_X     [cN * cE * cS];
__device__ float g_w     [cN * cE * cA];
__device__ float g_Epart [cN * cE * cNH];
__device__ float g_Apart6[KSPLIT_A * cN * cA * cNH];
__device__ float g_Apart [cN * cA * cNH];
__device__ __nv_bfloat16 g_entb[cN * cE * cD];   // bf16 operands for HMMA GEMM
__device__ __nv_bfloat16 g_tokb[cN * cE * cD];
__device__ __nv_bfloat16 g_Ahb [cN * cE * cD];
__device__ __nv_bfloat16 g_WTb [3 * cNH * cD];   // W blocks {0,2,3} as [n][k]

// ---------------- helpers ---------------------------------------------------
__device__ __forceinline__ void fma2(float2& d, float2 a, float2 b) {
    asm("fma.rn.f32x2 %0, %1, %2, %0;"
        : "+l"(reinterpret_cast<unsigned long long&>(d))
        : "l"(reinterpret_cast<unsigned long long&>(a)),
          "l"(reinterpret_cast<unsigned long long&>(b)));
}
__device__ __forceinline__ uint32_t smem_u32(const void* p) {
    return (uint32_t)__cvta_generic_to_shared(p);
}
__device__ __forceinline__ uint32_t lds32(uint32_t a) {
    uint32_t v;
    asm volatile("ld.shared.b32 %0, [%1];" : "=r"(v) : "r"(a));
    return v;
}
__device__ __forceinline__ void cp8(uint32_t dst, const void* src) {
    asm volatile("cp.async.ca.shared.global [%0], [%1], 8;"
                 :: "r"(dst), "l"(src));
}
__device__ __forceinline__ uint32_t pkbf(float a, float b) {
    __nv_bfloat162 h = __floats2bfloat162_rn(a, b);
    return *reinterpret_cast<uint32_t*>(&h);
}
__device__ __forceinline__ void mma16816(float* c, const uint32_t* a,
                                         uint32_t b0, uint32_t b1) {
    asm volatile(
        "mma.sync.aligned.m16n8k16.row.col.f32.bf16.bf16.f32 "
        "{%0,%1,%2,%3}, {%4,%5,%6,%7}, {%8,%9}, {%0,%1,%2,%3};"
        : "+f"(c[0]), "+f"(c[1]), "+f"(c[2]), "+f"(c[3])
        : "r"(a[0]), "r"(a[1]), "r"(a[2]), "r"(a[3]), "r"(b0), "r"(b1));
}

// ---------------- gather ----------------------------------------------------
__global__ void k_gather(const float* __restrict__ emb, const int* __restrict__ idxs) {
    int row = blockIdx.x, tid = threadIdx.x;  // 192 thr * float4
    if (row < cN * cS) {
        int n = row >> 7, s = row & 127;
        int src = idxs[n * cIDXW + s];
        ((float4*)(g_sent + (long)row * cD))[tid] =
            ((const float4*)(emb + ((long)n * cL + src) * cD))[tid];
    } else {
        int r = row - cN * cS, n = r / cA, a = r % cA;
        int src = idxs[n * cIDXW + cS] + 1 + a;
        ((float4*)(g_argraw + (long)r * cD))[tid] =
            ((const float4*)(emb + ((long)n * cL + src) * cD))[tid];
    }
}

// ---------------- t2t -------------------------------------------------------
__global__ void k_t2t(const float* __restrict__ attn, const int* __restrict__ idxs) {
    int n = blockIdx.x >> 7, a = blockIdx.x & 127;
    int b = threadIdx.x;
    __shared__ int   sc[cS];
    __shared__ float r0[cS], r1[cS], r2[cS];
    sc[b] = idxs[n * cIDXW + b];
    __syncthreads();
    int i = sc[a], j = sc[b];
    const long lstride = (long)cN * 12 * cL * cL;
    long base = ((long)n * 12) * (cL * cL) + (long)i * cL + j;
    float a0 = 0.f, a1 = 0.f, a2 = 0.f;
#pragma unroll
    for (int h = 0; h < 12; ++h) {
        long o = base + (long)h * (cL * cL);
        a0 += __ldg(attn + o);
        a1 += __ldg(attn + o + lstride);
        a2 += __ldg(attn + o + 2 * lstride);
    }
    r0[b] = a0; r1[b] = a1; r2[b] = a2;
    __syncthreads();
    for (int st = 64; st > 0; st >>= 1) {
        if (b < st) { r0[b] += r0[b + st]; r1[b] += r1[b + st]; r2[b] += r2[b + st]; }
        __syncthreads();
    }
    float d0 = r0[0] * (1.f / 12.f) + 1e-9f;
    float d1 = r1[0] * (1.f / 12.f) + 1e-9f;
    float d2 = r2[0] * (1.f / 12.f) + 1e-9f;
    g_t2t[((long)(n * cS + a)) * cS + b] =
        ((a0 * (1.f / 12.f)) / d0 + (a1 * (1.f / 12.f)) / d1 +
         (a2 * (1.f / 12.f)) / d2) * (1.f / 3.f);
}

// ---------------- arg_emb, a2a softmax, u2u ---------------------------------
__global__ void k_argsmall(const float* __restrict__ argw) {
    __shared__ float s_aw[cA * cA], s_ae[cA * cD], s_dot[cA * cA], s_a2a[cA * cA];
    int n = blockIdx.x, tid = threadIdx.x;   // 256
    if (tid < cA * cA) s_aw[tid] = argw[n * cA * cA + tid];
    __syncthreads();
    for (int idx = tid; idx < cA * cD; idx += 256) {
        int a = idx / cD, d = idx % cD;
        float acc = 0.f;
#pragma unroll
        for (int k = 0; k < cA; ++k)
            acc += g_argraw[((long)(n * cA + k)) * cD + d] * s_aw[k * cA + a];
        s_ae[a * cD + d] = acc;
        g_argemb[((long)(n * cA + a)) * cD + d] = acc;
    }
    __syncthreads();
    int wa = tid >> 5, lane = tid & 31;
    for (int p = wa; p < cA * cA; p += 8) {
        int a = p / cA, b = p % cA;
        float acc = 0.f;
        for (int r = lane; r < cD; r += 32) acc += s_ae[a * cD + r] * s_ae[b * cD + r];
        for (int o = 16; o > 0; o >>= 1) acc += __shfl_xor_sync(0xffffffffu, acc, o);
        if (lane == 0) s_dot[p] = acc;
    }
    __syncthreads();
    if (tid < cA) {
        float mx = -1e30f;
        for (int b = 0; b < cA; ++b) mx = fmaxf(mx, s_dot[tid * cA + b]);
        float e[cA], sum = 0.f;
        for (int b = 0; b < cA; ++b) { e[b] = expf(s_dot[tid * cA + b] - mx); sum += e[b]; }
        float inv = 1.f / sum;
        for (int b = 0; b < cA; ++b) s_a2a[tid * cA + b] = e[b] * inv;
    }
    __syncthreads();
    for (int idx = tid; idx < cA * cD; idx += 256) {
        int a = idx / cD, d = idx % cD;
        float acc = 0.f;
#pragma unroll
        for (int b = 0; b < cA; ++b) acc += s_a2a[a * cA + b] * s_ae[b * cD + d];
        g_u2u[((long)(n * cA + a)) * cD + d] = acc;
    }
}

// ---------------- W1 blocks {0,2,3}: transpose to bf16 [n][k] ---------------
__global__ void k_convW(const float* __restrict__ W1) {
    __shared__ float tile[32][33];
    int blk = blockIdx.z;                       // 0,1,2 -> W blocks 0,2,3
    int wb  = (blk == 0) ? 0 : (blk + 1);
    int tx = threadIdx.x, ty = threadIdx.y;     // 32 x 8
    const float* src = W1 + (long)wb * cD * cNH;
    int k0 = blockIdx.y * 32, n0 = blockIdx.x * 32;
#pragma unroll
    for (int j = 0; j < 4; ++j)
        tile[ty + j * 8][tx] = src[(long)(k0 + ty + j * 8) * cNH + n0 + tx];
    __syncthreads();
    __nv_bfloat16* Hi = g_WTb + (long)blk * cNH * cD;
#pragma unroll
    for (int j = 0; j < 4; ++j)
        Hi[(long)(n0 + ty + j * 8) * cD + k0 + tx] =
            __float2bfloat16_rn(tile[tx][ty + j * 8]);
}

// ---------------- SIMT GEMM for small roles ---------------------------------
// ROLE 0: ent = em^T@sent (fp32 + bf16 out); 1: X = em^T@t2t;
// ROLE 2: Ahb = X@sent (bf16 out only); 4: Apart partials splitK
template <int ROLE>
__global__ __launch_bounds__(256) void k_gemm(const float* __restrict__ PA,
                                              const float* __restrict__ PB) {
    constexpr bool ATRANS = (ROLE == 0 || ROLE == 1);
    constexpr int  NCH    = (ROLE == 4) ? 3 : 1;
    constexpr int  KSPL   = (ROLE == 4) ? KSPLIT_A : 1;
    constexpr int  BK     = 16;
    const float *Ap0 = nullptr, *Ap1 = nullptr, *Ap2 = nullptr;
    const float *Bp0 = nullptr, *Bp1 = nullptr, *Bp2 = nullptr;
    float* Cp = g_Epart;   // dummy default (never written for ROLE 2)
    long aStr = 0, bStr = 0, cStr = 0;
    int ldA = 0, ldB = 0, ldC = 0, M = 0, Kc = 0;
    if (ROLE == 0) { Ap0 = PA;     aStr = cS * cE; ldA = cE; Bp0 = g_sent; bStr = cS * cD;
                     ldB = cD; Cp = g_ent;  cStr = cE * cD; ldC = cD; M = cE; Kc = cS; }
    if (ROLE == 1) { Ap0 = PA;     aStr = cS * cE; ldA = cE; Bp0 = g_t2t;  bStr = cS * cS;
                     ldB = cS; Cp = g_X;    cStr = cE * cS; ldC = cS; M = cE; Kc = cS; }
    if (ROLE == 2) { Ap0 = g_X;    aStr = cE * cS; ldA = cS; Bp0 = g_sent; bStr = cS * cD;
                     ldB = cD; cStr = cE * cD; ldC = cD; M = cE; Kc = cS; }
    if (ROLE == 4) { Ap0 = g_argemb; Ap1 = g_atok; Ap2 = g_u2u; aStr = 0; ldA = cD;
                     Bp0 = PB + 1L * cD * cNH; Bp1 = PB + 4L * cD * cNH;
                     Bp2 = PB + 5L * cD * cNH; bStr = 0; ldB = cNH;
                     Cp = g_Apart6; cStr = 0; ldC = cNH; M = cN * cA; Kc = cD; }
    const float* Ap[3] = {Ap0, Ap1, Ap2};
    const float* Bp[3] = {Bp0, Bp1, Bp2};
    __shared__ float As[BK][68];
    __shared__ float Bs[BK][128];
    int z = blockIdx.z, n = z / KSPL, ks = z % KSPL;
    int m0 = blockIdx.x * 64, n0 = blockIdx.y * 128;
    int tid = threadIdx.x, tx = tid & 15, ty = tid >> 4;
    if (ROLE == 4) Cp += (long)ks * (cN * cA * cNH);
    float2 acc[4][4];
#pragma unroll
    for (int i = 0; i < 4; ++i)
#pragma unroll
        for (int p = 0; p < 4; ++p) acc[i][p] = make_float2(0.f, 0.f);
    int chB = 0, chE = NCH, koB = 0, koE = Kc;
    if (KSPL > 1) {
        constexpr int spc = KSPL / NCH;
        chB = ks / spc; chE = chB + 1;
        int len = Kc / spc;
        koB = (ks % spc) * len; koE = koB + len;
    }
    for (int ch = chB; ch < chE; ++ch) {
        const float* A = Ap[ch] + (long)n * aStr;
        const float* B = Bp[ch] + (long)n * bStr;
        for (int ko = koB; ko < koE; ko += BK) {
            if (ATRANS) {
                int r = tid >> 4, c4 = (tid & 15) << 2;
                float4 v = *(const float4*)(A + (long)(ko + r) * ldA + m0 + c4);
                As[r][c4] = v.x; As[r][c4 + 1] = v.y; As[r][c4 + 2] = v.z; As[r][c4 + 3] = v.w;
            } else {
                int m = tid >> 2, kq = (tid & 3) << 2;
                float4 v = make_float4(0.f, 0.f, 0.f, 0.f);
                if (m0 + m < M) v = *(const float4*)(A + (long)(m0 + m) * ldA + ko + kq);
                As[kq][m] = v.x; As[kq + 1][m] = v.y; As[kq + 2][m] = v.z; As[kq + 3][m] = v.w;
            }
            int r = tid >> 5, c4 = (tid & 31) << 2;
#pragma unroll
            for (int rr = 0; rr < 2; ++rr)
                *(float4*)&Bs[r + rr * 8][c4] =
                    *(const float4*)(B + (long)(ko + r + rr * 8) * ldB + n0 + c4);
            __syncthreads();
#pragma unroll
            for (int kk = 0; kk < BK; ++kk) {
                float4 av = *(const float4*)&As[kk][ty << 2];
                float a_[4] = {av.x, av.y, av.z, av.w};
                float2 b_[4];
#pragma unroll
                for (int p = 0; p < 4; ++p)
                    b_[p] = *(const float2*)&Bs[kk][(tx << 1) + (p << 5)];
#pragma unroll
                for (int i = 0; i < 4; ++i) {
                    float2 ad = make_float2(a_[i], a_[i]);
#pragma unroll
                    for (int p = 0; p < 4; ++p) fma2(acc[i][p], ad, b_[p]);
                }
            }
            __syncthreads();
        }
    }
    float* Cn = Cp + (long)n * cStr;
#pragma unroll
    for (int i = 0; i < 4; ++i) {
        int m = m0 + (ty << 2) + i;
        if (m < M) {
#pragma unroll
            for (int p = 0; p < 4; ++p) {
                int col = n0 + (tx << 1) + (p << 5);
                float2 v = acc[i][p];
                if (ROLE == 2) {
                    *(uint32_t*)&g_Ahb[((long)(n * cE + m)) * cD + col] = pkbf(v.x, v.y);
                } else {
                    *(float2*)&Cn[(long)m * ldC + col] = v;
                    if (ROLE == 0)
                        *(uint32_t*)&g_entb[((long)(n * cE + m)) * cD + col] = pkbf(v.x, v.y);
                }
            }
        }
    }
}

// ---------------- w / tok(bf16) / atok --------------------------------------
__global__ void k_w() {
    int n = blockIdx.x >> 7, e = blockIdx.x & 127;
    int wa = threadIdx.x >> 5, lane = threadIdx.x & 31;
    const float* er = g_ent + ((long)(n * cE + e)) * cD;
    const float* ar = g_argemb + ((long)(n * cA + wa)) * cD;
    float acc = 0.f;
    for (int r = lane; r < cD; r += 32) acc += er[r] * ar[r];
    for (int o = 16; o > 0; o >>= 1) acc += __shfl_xor_sync(0xffffffffu, acc, o);
    if (lane == 0)
        g_w[(n * cE + e) * cA + wa] = (acc * 0.03608439182435161f - 5.0f) * 0.5f;
}
__global__ void k_tok() {
    int n = blockIdx.x >> 7, e = blockIdx.x & 127;
    __shared__ float sw[cA];
    if (threadIdx.x < cA) sw[threadIdx.x] = g_w[(n * cE + e) * cA + threadIdx.x];
    __syncthreads();
    int d = threadIdx.x << 2;
    float4 acc = make_float4(0.f, 0.f, 0.f, 0.f);
#pragma unroll
    for (int a = 0; a < cA; ++a) {
        float4 v = *(const float4*)&g_argemb[((long)(n * cA + a)) * cD + d];
        float wv = sw[a];
        acc.x += wv * v.x; acc.y += wv * v.y; acc.z += wv * v.z; acc.w += wv * v.w;
    }
    uint2 o = make_uint2(pkbf(acc.x, acc.y), pkbf(acc.z, acc.w));
    *(uint2*)&g_tokb[((long)(n * cE + e)) * cD + d] = o;
}
__global__ void k_atok() {
    int n = blockIdx.x / cA, a = blockIdx.x % cA;
    int d = threadIdx.x << 2;
    float4 acc = make_float4(0.f, 0.f, 0.f, 0.f);
    for (int e = 0; e < cE; ++e) {
        float wv = g_w[(n * cE + e) * cA + a];
        float4 v = *(const float4*)&g_ent[((long)(n * cE + e)) * cD + d];
        acc.x += wv * v.x; acc.y += wv * v.y; acc.z += wv * v.z; acc.w += wv * v.w;
    }
    *(float4*)&g_atok[((long)(n * cA + a)) * cD + d] = acc;
}

// ---------------- HMMA Epart GEMM (bf16, mma.sync m16n8k16) -----------------
// Epart[2048,768] = entb@W0^T' + tokb@W2' + Ahb@W3'  (B stored [n][k])
constexpr int EP_ROW   = 80;                    // smem row stride bytes (40 bf16)
constexpr int EP_HALF  = 128 * EP_ROW;          // one operand (A or B) = 10240B
constexpr int EP_STAGE = 2 * EP_HALF;           // 20480
constexpr int EP_ITERS = 72;                    // 3 chunks * 768/32

__device__ __forceinline__ void ep_issue(int t, int buf, int m0, int n0,
                                         int tid, uint32_t smB) {
    int chunk = t / 24, k0 = (t % 24) * 32;
    const __nv_bfloat16* A = (chunk == 0) ? g_entb : (chunk == 1 ? g_tokb : g_Ahb);
    const __nv_bfloat16* B = g_WTb + (long)chunk * cNH * cD;
    uint32_t base = smB + buf * EP_STAGE;
#pragma unroll
    for (int j = 0; j < 4; ++j) {
        int g = tid + j * 256;               // 0..1023 granules of 8B
        int r = g >> 3, c8 = g & 7;          // c8*4 bf16
        cp8(base + r * EP_ROW + c8 * 8, A + (long)(m0 + r) * cD + k0 + c8 * 4);
        cp8(base + EP_HALF + r * EP_ROW + c8 * 8,
            B + (long)(n0 + r) * cD + k0 + c8 * 4);
    }
    asm volatile("cp.async.commit_group;" ::: "memory");
}

__global__ __launch_bounds__(256, 1) void k_epart_mma() {
    __shared__ __align__(16) char sm[2 * EP_STAGE];
    int tid = threadIdx.x, lane = tid & 31, wid = tid >> 5;
    int m0 = blockIdx.x * 128, n0 = blockIdx.y * 128;
    int warpM = (wid & 3) * 32, warpN = (wid >> 2) * 64;
    uint32_t smB = smem_u32(sm);

    float acc[2][8][4];
#pragma unroll
    for (int mi = 0; mi < 2; ++mi)
#pragma unroll
        for (int ni = 0; ni < 8; ++ni)
#pragma unroll
            for (int c = 0; c < 4; ++c) acc[mi][ni][c] = 0.f;

    ep_issue(0, 0, m0, n0, tid, smB);
    for (int t = 0; t < EP_ITERS; ++t) {
        int buf = t & 1;
        if (t + 1 < EP_ITERS) {
            ep_issue(t + 1, buf ^ 1, m0, n0, tid, smB);
            asm volatile("cp.async.wait_group 1;" ::: "memory");
        } else {
            asm volatile("cp.async.wait_group 0;" ::: "memory");
        }
        __syncthreads();
        uint32_t aS = smB + buf * EP_STAGE, bS = aS + EP_HALF;
#pragma unroll
        for (int ks = 0; ks < 32; ks += 16) {
            uint32_t afr[2][4];
#pragma unroll
            for (int mi = 0; mi < 2; ++mi) {
                uint32_t ab = aS + (warpM + mi * 16 + (lane >> 2)) * EP_ROW +
                              (ks + (lane & 3) * 2) * 2;
                afr[mi][0] = lds32(ab);
                afr[mi][1] = lds32(ab + 8 * EP_ROW);
                afr[mi][2] = lds32(ab + 16);
                afr[mi][3] = lds32(ab + 8 * EP_ROW + 16);
            }
#pragma unroll
            for (int ni = 0; ni < 8; ++ni) {
                uint32_t bb = bS + (warpN + ni * 8 + (lane >> 2)) * EP_ROW +
                              (ks + (lane & 3) * 2) * 2;
                uint32_t b0 = lds32(bb), b1 = lds32(bb + 16);
#pragma unroll
                for (int mi = 0; mi < 2; ++mi)
                    mma16816(acc[mi][ni], afr[mi], b0, b1);
            }
        }
        __syncthreads();
    }
#pragma unroll
    for (int mi = 0; mi < 2; ++mi) {
#pragma unroll
        for (int ni = 0; ni < 8; ++ni) {
            int r = m0 + warpM + mi * 16 + (lane >> 2);
            int c = n0 + warpN + ni * 8 + (lane & 3) * 2;
            *(float2*)&g_Epart[(long)r * cNH + c] =
                make_float2(acc[mi][ni][0], acc[mi][ni][1]);
            *(float2*)&g_Epart[(long)(r + 8) * cNH + c] =
                make_float2(acc[mi][ni][2], acc[mi][ni][3]);
        }
    }
}

// ---------------- split-K reduce + epilogue ---------------------------------
__global__ void k_redA() {
    int i = blockIdx.x * 256 + threadIdx.x;
    if (i < cN * cA * cNH) {
        float s = 0.f;
#pragma unroll
        for (int k = 0; k < KSPLIT_A; ++k) s += g_Apart6[(long)k * cN * cA * cNH + i];
        g_Apart[i] = s;
    }
}
__global__ void k_final(const float* __restrict__ b1, const float* __restrict__ W2,
                        const float* __restrict__ b2, const int* __restrict__ argmap,
                        float* __restrict__ out) {
    int n = blockIdx.x >> 7, e = blockIdx.x & 127;
    __shared__ float sEp[cNH];
    __shared__ float sScore[cA];
    int tid = threadIdx.x;   // 288
    for (int i = tid; i < cNH; i += 288)
        sEp[i] = g_Epart[((long)(n * cE + e)) * cNH + i];
    __syncthreads();
    int wa = tid >> 5, lane = tid & 31;
    {
        const float* ap = g_Apart + ((long)(n * cA + wa)) * cNH;
        float acc = 0.f;
        for (int r = lane; r < cNH; r += 32) {
            float pre = sEp[r] + ap[r] + b1[r];
            float h = 0.5f * pre * (1.0f + erff(pre * 0.7071067811865476f));
            acc += h * W2[r];
        }
        for (int o = 16; o > 0; o >>= 1) acc += __shfl_xor_sync(0xffffffffu, acc, o);
        if (lane == 0) sScore[wa] = acc + b2[0];
    }
    __syncthreads();
    if (tid < cROLES) {
        float v = -1000000.0f;
#pragma unroll
        for (int a = 0; a < cA; ++a)
            if (argmap[n * cA + a] == tid) v = sScore[a];
        out[((long)(n * cE + e)) * cROLES + tid] = v;
    }
}

// ---------------- launch ----------------------------------------------------
extern "C" void kernel_launch(void* const* d_in, const int* in_sizes, int n_in,
                              void* d_out, int out_size) {
    const float* emb  = (const float*)d_in[0];
    const float* attn = (const float*)d_in[1];
    const float* em   = (const float*)d_in[2];
    const float* argw = (const float*)d_in[3];
    const float* W1   = (const float*)d_in[5];
    const float* b1   = (const float*)d_in[6];
    const float* W2   = (const float*)d_in[7];
    const float* b2   = (const float*)d_in[8];
    const int*   idxs = (const int*)d_in[9];
    const int*   amap = (const int*)d_in[10];
    float* out = (float*)d_out;

    k_gather   <<<cN * (cS + cA), 192>>>(emb, idxs);
    k_t2t      <<<cN * cS, 128>>>(attn, idxs);
    k_argsmall <<<cN, 256>>>(argw);
    k_convW    <<<dim3(24, 24, 3), dim3(32, 8)>>>(W1);
    k_gemm<0>  <<<dim3(2, 6, cN), 256>>>(em, nullptr);
    k_gemm<1>  <<<dim3(2, 1, cN), 256>>>(em, nullptr);
    k_gemm<2>  <<<dim3(2, 6, cN), 256>>>(nullptr, nullptr);
    k_w        <<<cN * cE, 288>>>();
    k_tok      <<<cN * cE, 192>>>();
    k_atok     <<<cN * cA, 192>>>();
    k_epart_mma<<<dim3(16, 6), 256>>>();
    k_gemm<4>  <<<dim3(3, 6, KSPLIT_A), 256>>>(nullptr, W1);
    k_redA     <<<(cN * cA * cNH + 255) / 256, 256>>>();
    k_final    <<<cN * cE, 288>>>(b1, W2, b2, amap, out);
}

// round 5
// speedup vs baseline: 1.9924x; 1.0574x over previous
#include <cuda_runtime.h>
#include <cuda_bf16.h>
#include <cstdint>

constexpr int cN  = 16, cL = 256, cS = 128, cE = 128, cA = 9;
constexpr int cD  = 768, cNH = 768, cIDXW = 130, cROLES = 24;
constexpr int KSPL4 = 8;                 // role-4 split slices (4 chunks x 2)

// ---------------- scratch ---------------------------------------------------
__device__ float g_sent  [cN * cS * cD];
__device__ float g_argraw[cN * cA * cD];
__device__ float g_argemb[cN * cA * cD];
__device__ float g_u2u   [cN * cA * cD];
__device__ float g_atok  [cN * cA * cD];
__device__ float g_t2t   [cN * cS * cS];
__device__ float g_ent   [cN * cE * cD];
__device__ float g_X     [cN * cE * cS];
__device__ float g_w     [cN * cE * cA];
__device__ float g_Epart [cN * cE * cNH];
__device__ float g_Apart8[KSPL4 * cN * cA * cNH];
__device__ float g_Apart [cN * cA * cNH];
__device__ float g_Y2    [cN * cA * cNH];
// tiled+swizzled bf16 operands for the HMMA GEMM: 16KB tiles of 128x64
__device__ __nv_bfloat16 g_Atil[2 * cN * cE * cD];   // chunks {ent, Ah2h}
__device__ __nv_bfloat16 g_Btil[2 * cNH * cD];       // W blocks {0, 3} as [n][k]

// ---------------- helpers ---------------------------------------------------
__device__ __forceinline__ void fma2(float2& d, float2 a, float2 b) {
    asm("fma.rn.f32x2 %0, %1, %2, %0;"
        : "+l"(reinterpret_cast<unsigned long long&>(d))
        : "l"(reinterpret_cast<unsigned long long&>(a)),
          "l"(reinterpret_cast<unsigned long long&>(b)));
}
__device__ __forceinline__ uint32_t smem_u32(const void* p) {
    return (uint32_t)__cvta_generic_to_shared(p);
}
__device__ __forceinline__ uint32_t lds32(uint32_t a) {
    uint32_t v;
    asm volatile("ld.shared.b32 %0, [%1];" : "=r"(v) : "r"(a));
    return v;
}
__device__ __forceinline__ uint32_t pkbf(float a, float b) {
    __nv_bfloat162 h = __floats2bfloat162_rn(a, b);
    return *reinterpret_cast<uint32_t*>(&h);
}
__device__ __forceinline__ void mma16816(float* c, const uint32_t* a,
                                         uint32_t b0, uint32_t b1) {
    asm volatile(
        "mma.sync.aligned.m16n8k16.row.col.f32.bf16.bf16.f32 "
        "{%0,%1,%2,%3}, {%4,%5,%6,%7}, {%8,%9}, {%0,%1,%2,%3};"
        : "+f"(c[0]), "+f"(c[1]), "+f"(c[2]), "+f"(c[3])
        : "r"(a[0]), "r"(a[1]), "r"(a[2]), "r"(a[3]), "r"(b0), "r"(b1));
}
__device__ __forceinline__ void mbar_wait(uint32_t mbar, uint32_t parity) {
    uint32_t done;
    asm volatile("{\n\t.reg .pred p;\n\t"
        "mbarrier.try_wait.parity.acquire.cta.shared::cta.b64 p, [%1], %2;\n\t"
        "selp.b32 %0, 1, 0, p;\n\t}" : "=r"(done) : "r"(mbar), "r"(parity) : "memory");
    while (!done)
        asm volatile("{\n\t.reg .pred p;\n\t"
            "mbarrier.try_wait.parity.acquire.cta.shared::cta.b64 p, [%1], %2, 0x989680;\n\t"
            "selp.b32 %0, 1, 0, p;\n\t}" : "=r"(done) : "r"(mbar), "r"(parity) : "memory");
}

// ---------------- gather ----------------------------------------------------
__global__ void k_gather(const float* __restrict__ emb, const int* __restrict__ idxs) {
    int row = blockIdx.x, tid = threadIdx.x;  // 192 thr * float4
    if (row < cN * cS) {
        int n = row >> 7, s = row & 127;
        int src = idxs[n * cIDXW + s];
        ((float4*)(g_sent + (long)row * cD))[tid] =
            ((const float4*)(emb + ((long)n * cL + src) * cD))[tid];
    } else {
        int r = row - cN * cS, n = r / cA, a = r % cA;
        int src = idxs[n * cIDXW + cS] + 1 + a;
        ((float4*)(g_argraw + (long)r * cD))[tid] =
            ((const float4*)(emb + ((long)n * cL + src) * cD))[tid];
    }
}

// ---------------- t2t: coalesced smem preload -------------------------------
__global__ void k_t2t(const float* __restrict__ attn, const int* __restrict__ idxs) {
    int n = blockIdx.x >> 7, a = blockIdx.x & 127;
    int tid = threadIdx.x;                 // 128
    __shared__ float rows[36 * 256];
    __shared__ int   sc[cS];
    __shared__ float r0[cS], r1[cS], r2[cS];
    sc[tid] = idxs[n * cIDXW + tid];
    __syncthreads();
    int i = sc[a];
    for (int idx = tid; idx < 36 * 64; idx += 128) {
        int r = idx >> 6, c = idx & 63;        // r = l*12+h
        int l = r / 12, h = r - l * 12;
        long off = ((((long)l * cN + n) * 12 + h) * cL + i) * cL;
        *(float4*)&rows[r * 256 + c * 4] = *(const float4*)(attn + off + c * 4);
    }
    __syncthreads();
    int j = sc[tid];
    float a0 = 0.f, a1 = 0.f, a2 = 0.f;
#pragma unroll
    for (int h = 0; h < 12; ++h) {
        a0 += rows[h * 256 + j];
        a1 += rows[(12 + h) * 256 + j];
        a2 += rows[(24 + h) * 256 + j];
    }
    r0[tid] = a0; r1[tid] = a1; r2[tid] = a2;
    __syncthreads();
    for (int st = 64; st > 0; st >>= 1) {
        if (tid < st) { r0[tid] += r0[tid + st]; r1[tid] += r1[tid + st]; r2[tid] += r2[tid + st]; }
        __syncthreads();
    }
    float d0 = r0[0] * (1.f / 12.f) + 1e-9f;
    float d1 = r1[0] * (1.f / 12.f) + 1e-9f;
    float d2 = r2[0] * (1.f / 12.f) + 1e-9f;
    g_t2t[((long)(n * cS + a)) * cS + tid] =
        ((a0 * (1.f / 12.f)) / d0 + (a1 * (1.f / 12.f)) / d1 +
         (a2 * (1.f / 12.f)) / d2) * (1.f / 3.f);
}

// ---------------- arg_emb, a2a softmax, u2u ---------------------------------
__global__ void k_argsmall(const float* __restrict__ argw) {
    __shared__ float s_aw[cA * cA], s_ae[cA * cD], s_dot[cA * cA], s_a2a[cA * cA];
    int n = blockIdx.x, tid = threadIdx.x;   // 256
    if (tid < cA * cA) s_aw[tid] = argw[n * cA * cA + tid];
    __syncthreads();
    for (int idx = tid; idx < cA * cD; idx += 256) {
        int a = idx / cD, d = idx % cD;
        float acc = 0.f;
#pragma unroll
        for (int k = 0; k < cA; ++k)
            acc += g_argraw[((long)(n * cA + k)) * cD + d] * s_aw[k * cA + a];
        s_ae[a * cD + d] = acc;
        g_argemb[((long)(n * cA + a)) * cD + d] = acc;
    }
    __syncthreads();
    int wa = tid >> 5, lane = tid & 31;
    for (int p = wa; p < cA * cA; p += 8) {
        int a = p / cA, b = p % cA;
        float acc = 0.f;
        for (int r = lane; r < cD; r += 32) acc += s_ae[a * cD + r] * s_ae[b * cD + r];
        for (int o = 16; o > 0; o >>= 1) acc += __shfl_xor_sync(0xffffffffu, acc, o);
        if (lane == 0) s_dot[p] = acc;
    }
    __syncthreads();
    if (tid < cA) {
        float mx = -1e30f;
        for (int b = 0; b < cA; ++b) mx = fmaxf(mx, s_dot[tid * cA + b]);
        float e[cA], sum = 0.f;
        for (int b = 0; b < cA; ++b) { e[b] = expf(s_dot[tid * cA + b] - mx); sum += e[b]; }
        float inv = 1.f / sum;
        for (int b = 0; b < cA; ++b) s_a2a[tid * cA + b] = e[b] * inv;
    }
    __syncthreads();
    for (int idx = tid; idx < cA * cD; idx += 256) {
        int a = idx / cD, d = idx % cD;
        float acc = 0.f;
#pragma unroll
        for (int b = 0; b < cA; ++b) acc += s_a2a[a * cA + b] * s_ae[b * cD + d];
        g_u2u[((long)(n * cA + a)) * cD + d] = acc;
    }
}

// ---------------- W1 blocks {0,3} -> tiled swizzled bf16 B operand ----------
__global__ void k_convW(const float* __restrict__ W1) {
    __shared__ float tile[32][33];
    int blk = blockIdx.z;                       // 0 -> W0, 1 -> W3
    int wb  = (blk == 0) ? 0 : 3;
    int tx = threadIdx.x, ty = threadIdx.y;     // 32 x 8
    const float* src = W1 + (long)wb * cD * cNH;
    int k0 = blockIdx.y * 32, n0 = blockIdx.x * 32;
#pragma unroll
    for (int j = 0; j < 4; ++j)
        tile[ty + j * 8][tx] = src[(long)(k0 + ty + j * 8) * cNH + n0 + tx];
    __syncthreads();
#pragma unroll
    for (int j = 0; j < 4; ++j) {
        int nIdx = n0 + ty + j * 8, kIdx = k0 + tx;
        long off = (((long)(blk * 6 + (nIdx >> 7)) * 12 + (kIdx >> 6)) * 128 +
                    (nIdx & 127)) * 128 +
                   (((kIdx & 63) * 2) ^ ((nIdx & 7) << 4));
        *(__nv_bfloat16*)((char*)g_Btil + off) = __float2bfloat16_rn(tile[tx][ty + j * 8]);
    }
}

// ---------------- SIMT GEMM for small roles ---------------------------------
// ROLE 0: ent = em^T@sent (fp32 + tiled bf16); 1: X = em^T@t2t;
// ROLE 2: Ah2h = X@sent (tiled bf16 only); 4: Apart/Y2 slices (splitK 8)
template <int ROLE>
__global__ __launch_bounds__(256) void k_gemm(const float* __restrict__ PA,
                                              const float* __restrict__ PB) {
    constexpr bool ATRANS = (ROLE == 0 || ROLE == 1);
    constexpr int  NCH    = (ROLE == 4) ? 4 : 1;
    constexpr int  KSPL   = (ROLE == 4) ? KSPL4 : 1;
    constexpr int  BK     = 16;
    const float *Ap0 = nullptr, *Ap1 = nullptr, *Ap2 = nullptr, *Ap3 = nullptr;
    const float *Bp0 = nullptr, *Bp1 = nullptr, *Bp2 = nullptr, *Bp3 = nullptr;
    float* Cp = g_Epart;   // dummy default (never written for ROLE 2)
    long aStr = 0, bStr = 0, cStr = 0;
    int ldA = 0, ldB = 0, ldC = 0, M = 0, Kc = 0;
    if (ROLE == 0) { Ap0 = PA;     aStr = cS * cE; ldA = cE; Bp0 = g_sent; bStr = cS * cD;
                     ldB = cD; Cp = g_ent;  cStr = cE * cD; ldC = cD; M = cE; Kc = cS; }
    if (ROLE == 1) { Ap0 = PA;     aStr = cS * cE; ldA = cE; Bp0 = g_t2t;  bStr = cS * cS;
                     ldB = cS; Cp = g_X;    cStr = cE * cS; ldC = cS; M = cE; Kc = cS; }
    if (ROLE == 2) { Ap0 = g_X;    aStr = cE * cS; ldA = cS; Bp0 = g_sent; bStr = cS * cD;
                     ldB = cD; cStr = cE * cD; ldC = cD; M = cE; Kc = cS; }
    if (ROLE == 4) { Ap0 = g_argemb; Ap1 = g_atok; Ap2 = g_u2u; Ap3 = g_argemb;
                     aStr = 0; ldA = cD;
                     Bp0 = PB + 1L * cD * cNH; Bp1 = PB + 4L * cD * cNH;
                     Bp2 = PB + 5L * cD * cNH; Bp3 = PB + 2L * cD * cNH;
                     bStr = 0; ldB = cNH;
                     Cp = g_Apart8; cStr = 0; ldC = cNH; M = cN * cA; Kc = cD; }
    const float* Ap[4] = {Ap0, Ap1, Ap2, Ap3};
    const float* Bp[4] = {Bp0, Bp1, Bp2, Bp3};
    __shared__ float As[BK][68];
    __shared__ float Bs[BK][128];
    int z = blockIdx.z, n = z / KSPL, ks = z % KSPL;
    int m0 = blockIdx.x * 64, n0 = blockIdx.y * 128;
    int tid = threadIdx.x, tx = tid & 15, ty = tid >> 4;
    if (ROLE == 4) Cp += (long)ks * (cN * cA * cNH);
    float2 acc[4][4];
#pragma unroll
    for (int i = 0; i < 4; ++i)
#pragma unroll
        for (int p = 0; p < 4; ++p) acc[i][p] = make_float2(0.f, 0.f);
    int chB = 0, chE = NCH, koB = 0, koE = Kc;
    if (KSPL > 1) {
        constexpr int spc = KSPL / NCH;   // 2
        chB = ks / spc; chE = chB + 1;
        int len = Kc / spc;
        koB = (ks % spc) * len; koE = koB + len;
    }
    for (int ch = chB; ch < chE; ++ch) {
        const float* A = Ap[ch] + (long)n * aStr;
        const float* B = Bp[ch] + (long)n * bStr;
        for (int ko = koB; ko < koE; ko += BK) {
            if (ATRANS) {
                int r = tid >> 4, c4 = (tid & 15) << 2;
                float4 v = *(const float4*)(A + (long)(ko + r) * ldA + m0 + c4);
                As[r][c4] = v.x; As[r][c4 + 1] = v.y; As[r][c4 + 2] = v.z; As[r][c4 + 3] = v.w;
            } else {
                int m = tid >> 2, kq = (tid & 3) << 2;
                float4 v = make_float4(0.f, 0.f, 0.f, 0.f);
                if (m0 + m < M) v = *(const float4*)(A + (long)(m0 + m) * ldA + ko + kq);
                As[kq][m] = v.x; As[kq + 1][m] = v.y; As[kq + 2][m] = v.z; As[kq + 3][m] = v.w;
            }
            int r = tid >> 5, c4 = (tid & 31) << 2;
#pragma unroll
            for (int rr = 0; rr < 2; ++rr)
                *(float4*)&Bs[r + rr * 8][c4] =
                    *(const float4*)(B + (long)(ko + r + rr * 8) * ldB + n0 + c4);
            __syncthreads();
#pragma unroll
            for (int kk = 0; kk < BK; ++kk) {
                float4 av = *(const float4*)&As[kk][ty << 2];
                float a_[4] = {av.x, av.y, av.z, av.w};
                float2 b_[4];
#pragma unroll
                for (int p = 0; p < 4; ++p)
                    b_[p] = *(const float2*)&Bs[kk][(tx << 1) + (p << 5)];
#pragma unroll
                for (int i = 0; i < 4; ++i) {
                    float2 ad = make_float2(a_[i], a_[i]);
#pragma unroll
                    for (int p = 0; p < 4; ++p) fma2(acc[i][p], ad, b_[p]);
                }
            }
            __syncthreads();
        }
    }
    float* Cn = Cp + (long)n * cStr;
#pragma unroll
    for (int i = 0; i < 4; ++i) {
        int m = m0 + (ty << 2) + i;
        if (m < M) {
#pragma unroll
            for (int p = 0; p < 4; ++p) {
                int col = n0 + (tx << 1) + (p << 5);
                float2 v = acc[i][p];
                if (ROLE == 0 || ROLE == 2) {
                    // tiled swizzled bf16 write (chunk 0 = ent, chunk 1 = Ah2h)
                    int chunk = (ROLE == 0) ? 0 : 1;
                    long off = (((long)((chunk * 16 + n) * 12 + (col >> 6))) * 128 + m) * 128 +
                               (((col & 63) * 2) ^ ((m & 7) << 4));
                    *(uint32_t*)((char*)g_Atil + off) = pkbf(v.x, v.y);
                    if (ROLE == 0)
                        *(float2*)&Cn[(long)m * ldC + col] = v;
                } else {
                    *(float2*)&Cn[(long)m * ldC + col] = v;
                }
            }
        }
    }
}

// ---------------- w / atok --------------------------------------------------
__global__ void k_w() {
    int n = blockIdx.x >> 7, e = blockIdx.x & 127;
    int wa = threadIdx.x >> 5, lane = threadIdx.x & 31;
    const float* er = g_ent + ((long)(n * cE + e)) * cD;
    const float* ar = g_argemb + ((long)(n * cA + wa)) * cD;
    float acc = 0.f;
    for (int r = lane; r < cD; r += 32) acc += er[r] * ar[r];
    for (int o = 16; o > 0; o >>= 1) acc += __shfl_xor_sync(0xffffffffu, acc, o);
    if (lane == 0)
        g_w[(n * cE + e) * cA + wa] = (acc * 0.03608439182435161f - 5.0f) * 0.5f;
}
__global__ void k_atok() {
    int n = blockIdx.x / cA, a = blockIdx.x % cA;
    int d = threadIdx.x << 2;
    float4 acc = make_float4(0.f, 0.f, 0.f, 0.f);
    for (int e = 0; e < cE; ++e) {
        float wv = g_w[(n * cE + e) * cA + a];
        float4 v = *(const float4*)&g_ent[((long)(n * cE + e)) * cD + d];
        acc.x += wv * v.x; acc.y += wv * v.y; acc.z += wv * v.z; acc.w += wv * v.w;
    }
    *(float4*)&g_atok[((long)(n * cA + a)) * cD + d] = acc;
}

// ---------------- HMMA Epart GEMM: bulk-copy pipeline -----------------------
// Epart[2048,768] = ent@W0 + Ah2h@W3 ; operands pre-tiled 16KB, swizzled.
constexpr int EP_TILE  = 16384;
constexpr int EP_STG   = 2 * EP_TILE;
constexpr int EP_NST   = 3;
constexpr int EP_SMEM  = 128 + EP_NST * EP_STG;   // 98432
constexpr int EP_ITERS = 24;                      // 2 chunks * 12 ktiles

__global__ __launch_bounds__(256, 1) void k_epart_mma() {
    extern __shared__ __align__(128) char sm[];
    uint32_t smB = smem_u32(sm);
    int tid = threadIdx.x, lane = tid & 31, wid = tid >> 5;
    int mt = blockIdx.x, nt = blockIdx.y;
    int warpM = (wid & 3) * 32, warpN = (wid >> 2) * 64;

    if (tid == 0)
        for (int s = 0; s < EP_NST; ++s)
            asm volatile("mbarrier.init.shared.b64 [%0], 1;" :: "r"(smB + s * 8) : "memory");
    __syncthreads();

    auto issue = [&](int t, int stg) {
        int chunk = t / 12, kt = t % 12;
        const char* srcA = (const char*)g_Atil +
            ((long)((chunk * 16 + mt) * 12 + kt)) * EP_TILE;
        const char* srcB = (const char*)g_Btil +
            ((long)((chunk * 6 + nt) * 12 + kt)) * EP_TILE;
        uint32_t mbar = smB + stg * 8;
        uint32_t dst  = smB + 128 + stg * EP_STG;
        asm volatile("mbarrier.arrive.expect_tx.shared.b64 _, [%0], %1;"
                     :: "r"(mbar), "r"((uint32_t)EP_STG) : "memory");
        asm volatile("cp.async.bulk.shared::cta.global.mbarrier::complete_tx::bytes "
                     "[%0], [%1], %2, [%3];"
                     :: "r"(dst), "l"(srcA), "r"((uint32_t)EP_TILE), "r"(mbar) : "memory");
        asm volatile("cp.async.bulk.shared::cta.global.mbarrier::complete_tx::bytes "
                     "[%0], [%1], %2, [%3];"
                     :: "r"(dst + EP_TILE), "l"(srcB), "r"((uint32_t)EP_TILE), "r"(mbar) : "memory");
    };
    if (tid == 0) { issue(0, 0); issue(1, 1); issue(2, 2); }

    float acc[2][8][4];
#pragma unroll
    for (int mi = 0; mi < 2; ++mi)
#pragma unroll
        for (int ni = 0; ni < 8; ++ni)
#pragma unroll
            for (int c = 0; c < 4; ++c) acc[mi][ni][c] = 0.f;

    uint32_t ph[EP_NST] = {0, 0, 0};
    for (int t = 0; t < EP_ITERS; ++t) {
        int stg = t % EP_NST;
        mbar_wait(smB + stg * 8, ph[stg]);
        ph[stg] ^= 1;
        uint32_t aS = smB + 128 + stg * EP_STG, bS = aS + EP_TILE;
#pragma unroll
        for (int ks = 0; ks < 64; ks += 16) {
            uint32_t kb = (uint32_t)((ks + (lane & 3) * 2) * 2);
            uint32_t afr[2][4];
#pragma unroll
            for (int mi = 0; mi < 2; ++mi) {
                int row = warpM + mi * 16 + (lane >> 2);
                uint32_t x = (uint32_t)(row & 7) << 4;
                uint32_t p0 = aS + row * 128 + (kb ^ x);
                uint32_t p1 = aS + row * 128 + ((kb + 16) ^ x);
                afr[mi][0] = lds32(p0);
                afr[mi][1] = lds32(p0 + 1024);
                afr[mi][2] = lds32(p1);
                afr[mi][3] = lds32(p1 + 1024);
            }
#pragma unroll
            for (int ni = 0; ni < 8; ++ni) {
                int row = warpN + ni * 8 + (lane >> 2);
                uint32_t x = (uint32_t)(row & 7) << 4;
                uint32_t b0 = lds32(bS + row * 128 + (kb ^ x));
                uint32_t b1 = lds32(bS + row * 128 + ((kb + 16) ^ x));
                mma16816(acc[0][ni], afr[0], b0, b1);
                mma16816(acc[1][ni], afr[1], b0, b1);
            }
        }
        __syncthreads();
        if (t + EP_NST < EP_ITERS && tid == 0) issue(t + EP_NST, stg);
    }
#pragma unroll
    for (int mi = 0; mi < 2; ++mi) {
#pragma unroll
        for (int ni = 0; ni < 8; ++ni) {
            int r = mt * 128 + warpM + mi * 16 + (lane >> 2);
            int c = nt * 128 + warpN + ni * 8 + (lane & 3) * 2;
            *(float2*)&g_Epart[(long)r * cNH + c] =
                make_float2(acc[mi][ni][0], acc[mi][ni][1]);
            *(float2*)&g_Epart[(long)(r + 8) * cNH + c] =
                make_float2(acc[mi][ni][2], acc[mi][ni][3]);
        }
    }
}

// ---------------- split-K reduce: Apart + Y2 --------------------------------
__global__ void k_redA() {
    int i = blockIdx.x * 256 + threadIdx.x;
    constexpr int SZ = cN * cA * cNH;
    if (i < SZ) {
        float s = 0.f;
#pragma unroll
        for (int k = 0; k < 6; ++k) s += g_Apart8[(long)k * SZ + i];
        g_Apart[i] = s;
        g_Y2[i] = g_Apart8[6L * SZ + i] + g_Apart8[7L * SZ + i];
    }
}

// ---------------- epilogue: +w@Y2, gelu, score, scatter ---------------------
__global__ void k_final(const float* __restrict__ b1, const float* __restrict__ W2,
                        const float* __restrict__ b2, const int* __restrict__ argmap,
                        float* __restrict__ out) {
    int n = blockIdx.x >> 7, e = blockIdx.x & 127;
    __shared__ float sEp[cNH];
    __shared__ float sw9[cA];
    __shared__ float sScore[cA];
    int tid = threadIdx.x;   // 288
    if (tid < cA) sw9[tid] = g_w[(n * cE + e) * cA + tid];
    __syncthreads();
    for (int r = tid; r < cNH; r += 288) {
        float s = g_Epart[((long)(n * cE + e)) * cNH + r] + b1[r];
#pragma unroll
        for (int a = 0; a < cA; ++a) s += sw9[a] * g_Y2[((long)(n * cA + a)) * cNH + r];
        sEp[r] = s;
    }
    __syncthreads();
    int wa = tid >> 5, lane = tid & 31;
    {
        const float* ap = g_Apart + ((long)(n * cA + wa)) * cNH;
        float acc = 0.f;
        for (int r = lane; r < cNH; r += 32) {
            float pre = sEp[r] + ap[r];
            float h = 0.5f * pre * (1.0f + erff(pre * 0.7071067811865476f));
            acc += h * W2[r];
        }
        for (int o = 16; o > 0; o >>= 1) acc += __shfl_xor_sync(0xffffffffu, acc, o);
        if (lane == 0) sScore[wa] = acc + b2[0];
    }
    __syncthreads();
    if (tid < cROLES) {
        float v = -1000000.0f;
#pragma unroll
        for (int a = 0; a < cA; ++a)
            if (argmap[n * cA + a] == tid) v = sScore[a];
        out[((long)(n * cE + e)) * cROLES + tid] = v;
    }
}

// ---------------- launch ----------------------------------------------------
extern "C" void kernel_launch(void* const* d_in, const int* in_sizes, int n_in,
                              void* d_out, int out_size) {
    const float* emb  = (const float*)d_in[0];
    const float* attn = (const float*)d_in[1];
    const float* em   = (const float*)d_in[2];
    const float* argw = (const float*)d_in[3];
    const float* W1   = (const float*)d_in[5];
    const float* b1   = (const float*)d_in[6];
    const float* W2   = (const float*)d_in[7];
    const float* b2   = (const float*)d_in[8];
    const int*   idxs = (const int*)d_in[9];
    const int*   amap = (const int*)d_in[10];
    float* out = (float*)d_out;

    cudaFuncSetAttribute(k_epart_mma, cudaFuncAttributeMaxDynamicSharedMemorySize, EP_SMEM);

    k_gather   <<<cN * (cS + cA), 192>>>(emb, idxs);
    k_t2t      <<<cN * cS, 128>>>(attn, idxs);
    k_argsmall <<<cN, 256>>>(argw);
    k_convW    <<<dim3(24, 24, 2), dim3(32, 8)>>>(W1);
    k_gemm<0>  <<<dim3(2, 6, cN), 256>>>(em, nullptr);
    k_gemm<1>  <<<dim3(2, 1, cN), 256>>>(em, nullptr);
    k_gemm<2>  <<<dim3(2, 6, cN), 256>>>(nullptr, nullptr);
    k_w        <<<cN * cE, 288>>>();
    k_atok     <<<cN * cA, 192>>>();
    k_epart_mma<<<dim3(16, 6), 256, EP_SMEM>>>();
    k_gemm<4>  <<<dim3(3, 6, KSPL4), 256>>>(nullptr, W1);
    k_redA     <<<(cN * cA * cNH + 255) / 256, 256>>>();
    k_final    <<<cN * cE, 288>>>(b1, W2, b2, amap, out);
}

// round 6
// speedup vs baseline: 2.2957x; 1.1522x over previous
#include <cuda_runtime.h>
#include <cuda_bf16.h>
#include <cstdint>

constexpr int cN  = 16, cL = 256, cS = 128, cE = 128, cA = 9;
constexpr int cD  = 768, cNH = 768, cIDXW = 130, cROLES = 24;
constexpr int cM  = cN * cA;            // 144
constexpr int SZA = cM * cNH;           // 110592

// ---------------- scratch ---------------------------------------------------
__device__ float g_sent  [cN * cS * cD];
__device__ float g_argraw[cN * cA * cD];
__device__ float g_argemb[cN * cA * cD];
__device__ float g_u2u   [cN * cA * cD];
__device__ float g_atok  [cN * cA * cD];
__device__ float g_t2t   [cN * cS * cS];
__device__ float g_ent   [cN * cE * cD];
__device__ float g_X     [cN * cE * cS];
__device__ float g_w     [cN * cE * cA];
__device__ float g_Epart [cN * cE * cNH];
__device__ float g_Apart8[6 * SZA];     // slices: 0-3 Apart(W1,W5), 4-5 Y2(W2)
__device__ float g_ApartE[SZA];
__device__ float g_AtokW4[SZA];
__device__ float g_Y2    [SZA];
__device__ __nv_bfloat16 g_Atil[2 * cN * cE * cD];   // tiled bf16 {ent, Ah2h}
__device__ __nv_bfloat16 g_Btil[2 * cNH * cD];       // tiled bf16 W {0,3}

// ---------------- helpers ---------------------------------------------------
__device__ __forceinline__ void fma2(float2& d, float2 a, float2 b) {
    asm("fma.rn.f32x2 %0, %1, %2, %0;"
        : "+l"(reinterpret_cast<unsigned long long&>(d))
        : "l"(reinterpret_cast<unsigned long long&>(a)),
          "l"(reinterpret_cast<unsigned long long&>(b)));
}
__device__ __forceinline__ uint32_t smem_u32(const void* p) {
    return (uint32_t)__cvta_generic_to_shared(p);
}
__device__ __forceinline__ uint32_t lds32(uint32_t a) {
    uint32_t v;
    asm volatile("ld.shared.b32 %0, [%1];" : "=r"(v) : "r"(a));
    return v;
}
__device__ __forceinline__ uint32_t pkbf(float a, float b) {
    __nv_bfloat162 h = __floats2bfloat162_rn(a, b);
    return *reinterpret_cast<uint32_t*>(&h);
}
__device__ __forceinline__ void mma16816(float* c, const uint32_t* a,
                                         uint32_t b0, uint32_t b1) {
    asm volatile(
        "mma.sync.aligned.m16n8k16.row.col.f32.bf16.bf16.f32 "
        "{%0,%1,%2,%3}, {%4,%5,%6,%7}, {%8,%9}, {%0,%1,%2,%3};"
        : "+f"(c[0]), "+f"(c[1]), "+f"(c[2]), "+f"(c[3])
        : "r"(a[0]), "r"(a[1]), "r"(a[2]), "r"(a[3]), "r"(b0), "r"(b1));
}
__device__ __forceinline__ void mbar_wait(uint32_t mbar, uint32_t parity) {
    uint32_t done;
    asm volatile("{\n\t.reg .pred p;\n\t"
        "mbarrier.try_wait.parity.acquire.cta.shared::cta.b64 p, [%1], %2;\n\t"
        "selp.b32 %0, 1, 0, p;\n\t}" : "=r"(done) : "r"(mbar), "r"(parity) : "memory");
    while (!done)
        asm volatile("{\n\t.reg .pred p;\n\t"
            "mbarrier.try_wait.parity.acquire.cta.shared::cta.b64 p, [%1], %2, 0x989680;\n\t"
            "selp.b32 %0, 1, 0, p;\n\t}" : "=r"(done) : "r"(mbar), "r"(parity) : "memory");
}

// ======================= role device functions ==============================

// ---- gather (256 thr, 192 active) ----
__device__ void dev_gather(int row, const float* __restrict__ emb,
                           const int* __restrict__ idxs) {
    int tid = threadIdx.x;
    if (tid >= 192) return;
    if (row < cN * cS) {
        int n = row >> 7, s = row & 127;
        int src = idxs[n * cIDXW + s];
        ((float4*)(g_sent + (long)row * cD))[tid] =
            ((const float4*)(emb + ((long)n * cL + src) * cD))[tid];
    } else {
        int r = row - cN * cS, n = r / cA, a = r % cA;
        int src = idxs[n * cIDXW + cS] + 1 + a;
        ((float4*)(g_argraw + (long)r * cD))[tid] =
            ((const float4*)(emb + ((long)n * cL + src) * cD))[tid];
    }
}

// ---- t2t (256 thr) ----
__device__ void dev_t2t(char* sm, int bid, const float* __restrict__ attn,
                        const int* __restrict__ idxs) {
    float* rows = (float*)sm;                    // 36*256
    int*   sc   = (int*)(sm + 36864);            // 128
    float* r0   = (float*)(sm + 37376);
    float* r1   = (float*)(sm + 37888);
    float* r2   = (float*)(sm + 38400);
    int n = bid >> 7, a = bid & 127;
    int tid = threadIdx.x;
    if (tid < cS) sc[tid] = idxs[n * cIDXW + tid];
    __syncthreads();
    int i = sc[a];
    for (int idx = tid; idx < 36 * 64; idx += 256) {
        int r = idx >> 6, c = idx & 63;
        int l = r / 12, h = r - l * 12;
        long off = ((((long)l * cN + n) * 12 + h) * cL + i) * cL;
        *(float4*)&rows[r * 256 + c * 4] = *(const float4*)(attn + off + c * 4);
    }
    __syncthreads();
    float a0 = 0.f, a1 = 0.f, a2 = 0.f;
    if (tid < cS) {
        int j = sc[tid];
#pragma unroll
        for (int h = 0; h < 12; ++h) {
            a0 += rows[h * 256 + j];
            a1 += rows[(12 + h) * 256 + j];
            a2 += rows[(24 + h) * 256 + j];
        }
        r0[tid] = a0; r1[tid] = a1; r2[tid] = a2;
    }
    __syncthreads();
    for (int st = 64; st > 0; st >>= 1) {
        if (tid < st) { r0[tid] += r0[tid + st]; r1[tid] += r1[tid + st]; r2[tid] += r2[tid + st]; }
        __syncthreads();
    }
    if (tid < cS) {
        float d0 = r0[0] * (1.f / 12.f) + 1e-9f;
        float d1 = r1[0] * (1.f / 12.f) + 1e-9f;
        float d2 = r2[0] * (1.f / 12.f) + 1e-9f;
        g_t2t[((long)(n * cS + a)) * cS + tid] =
            ((a0 * (1.f / 12.f)) / d0 + (a1 * (1.f / 12.f)) / d1 +
             (a2 * (1.f / 12.f)) / d2) * (1.f / 3.f);
    }
}

// ---- convW: W1 blocks {0,3} -> tiled swizzled bf16 ----
__device__ void dev_convW(char* sm, int bid, const float* __restrict__ W1) {
    float (*tile)[33] = (float(*)[33])sm;
    int bx = bid % 24, by = (bid / 24) % 24, blk = bid / 576;
    int wb = (blk == 0) ? 0 : 3;
    int tid = threadIdx.x, tx = tid & 31, ty = tid >> 5;   // 32 x 8
    const float* src = W1 + (long)wb * cD * cNH;
    int k0 = by * 32, n0 = bx * 32;
#pragma unroll
    for (int j = 0; j < 4; ++j)
        tile[ty + j * 8][tx] = src[(long)(k0 + ty + j * 8) * cNH + n0 + tx];
    __syncthreads();
#pragma unroll
    for (int j = 0; j < 4; ++j) {
        int nIdx = n0 + ty + j * 8, kIdx = k0 + tx;
        long off = (((long)(blk * 6 + (nIdx >> 7)) * 12 + (kIdx >> 6)) * 128 +
                    (nIdx & 127)) * 128 +
                   (((kIdx & 63) * 2) ^ ((nIdx & 7) << 4));
        *(__nv_bfloat16*)((char*)g_Btil + off) = __float2bfloat16_rn(tile[tx][ty + j * 8]);
    }
}

// ---- argsmall ----
__device__ void dev_argsmall(char* sm, int n, const float* __restrict__ argw) {
    float* s_ae  = (float*)sm;                   // 9*768
    float* s_aw  = (float*)(sm + 27648);
    float* s_dot = (float*)(sm + 27984);
    float* s_a2a = (float*)(sm + 28320);
    int tid = threadIdx.x;
    if (tid < cA * cA) s_aw[tid] = argw[n * cA * cA + tid];
    __syncthreads();
    for (int idx = tid; idx < cA * cD; idx += 256) {
        int a = idx / cD, d = idx % cD;
        float acc = 0.f;
#pragma unroll
        for (int k = 0; k < cA; ++k)
            acc += g_argraw[((long)(n * cA + k)) * cD + d] * s_aw[k * cA + a];
        s_ae[a * cD + d] = acc;
        g_argemb[((long)(n * cA + a)) * cD + d] = acc;
    }
    __syncthreads();
    int wa = tid >> 5, lane = tid & 31;
    for (int p = wa; p < cA * cA; p += 8) {
        int a = p / cA, b = p % cA;
        float acc = 0.f;
        for (int r = lane; r < cD; r += 32) acc += s_ae[a * cD + r] * s_ae[b * cD + r];
        for (int o = 16; o > 0; o >>= 1) acc += __shfl_xor_sync(0xffffffffu, acc, o);
        if (lane == 0) s_dot[p] = acc;
    }
    __syncthreads();
    if (tid < cA) {
        float mx = -1e30f;
        for (int b = 0; b < cA; ++b) mx = fmaxf(mx, s_dot[tid * cA + b]);
        float e[cA], sum = 0.f;
        for (int b = 0; b < cA; ++b) { e[b] = expf(s_dot[tid * cA + b] - mx); sum += e[b]; }
        float inv = 1.f / sum;
        for (int b = 0; b < cA; ++b) s_a2a[tid * cA + b] = e[b] * inv;
    }
    __syncthreads();
    for (int idx = tid; idx < cA * cD; idx += 256) {
        int a = idx / cD, d = idx % cD;
        float acc = 0.f;
#pragma unroll
        for (int b = 0; b < cA; ++b) acc += s_a2a[a * cA + b] * s_ae[b * cD + d];
        g_u2u[((long)(n * cA + a)) * cD + d] = acc;
    }
}

// ---- SIMT GEMM with register double-buffering ----
// ROLE 0: ent=em^T@sent (fp32+Atil); 1: X=em^T@t2t; 2: Ah2h=X@sent (Atil only)
// ROLE 4: early Apart slices {argemb@W1,u2u@W5,argemb@W2} splitK2; 5: atok@W4 full
template <int ROLE>
__device__ void dev_gemm(char* smraw, int bx, int by, int bz,
                         const float* __restrict__ PA, const float* __restrict__ PB) {
    constexpr bool ATRANS = (ROLE == 0 || ROLE == 1);
    constexpr int BK = 16;
    float (*As)[68]  = reinterpret_cast<float(*)[68]>(smraw);
    float (*Bs)[128] = reinterpret_cast<float(*)[128]>(smraw + BK * 68 * 4);

    const float* A = nullptr; const float* B = nullptr; float* Cout = nullptr;
    int ldA = 0, ldB = 0, M = 0, n = 0, koB = 0, koE = 0;
    if (ROLE == 0) { n = bz; A = PA + (long)n * cS * cE; ldA = cE;
                     B = g_sent + (long)n * cS * cD; ldB = cD; M = cE; koE = cS; }
    if (ROLE == 1) { n = bz; A = PA + (long)n * cS * cE; ldA = cE;
                     B = g_t2t + (long)n * cS * cS; ldB = cS; M = cE; koE = cS; }
    if (ROLE == 2) { n = bz; A = g_X + (long)n * cE * cS; ldA = cS;
                     B = g_sent + (long)n * cS * cD; ldB = cD; M = cE; koE = cS; }
    if (ROLE == 4) { int chunk = bz >> 1, kh = bz & 1;
                     A = (chunk == 1) ? g_u2u : g_argemb; ldA = cD;
                     int wblk = (chunk == 0) ? 1 : (chunk == 1 ? 5 : 2);
                     B = PB + (long)wblk * cD * cNH; ldB = cNH; M = cM;
                     koB = kh * 384; koE = koB + 384;
                     Cout = g_Apart8 + (long)bz * SZA; }
    if (ROLE == 5) { A = g_atok; ldA = cD;
                     B = PB + 4L * cD * cNH; ldB = cNH; M = cM;
                     koE = cD; Cout = g_AtokW4; }
    int m0 = bx * 64, n0 = by * 128;
    int tid = threadIdx.x, tx = tid & 15, ty = tid >> 4;

    float2 acc[4][4];
#pragma unroll
    for (int i = 0; i < 4; ++i)
#pragma unroll
        for (int p = 0; p < 4; ++p) acc[i][p] = make_float2(0.f, 0.f);

    auto ldA_t = [&](int ko) -> float4 {
        if (ATRANS) {
            int r = tid >> 4, c4 = (tid & 15) << 2;
            return *(const float4*)(A + (long)(ko + r) * ldA + m0 + c4);
        } else {
            int m = tid >> 2, kq = (tid & 3) << 2;
            if (m0 + m < M) return *(const float4*)(A + (long)(m0 + m) * ldA + ko + kq);
            return make_float4(0.f, 0.f, 0.f, 0.f);
        }
    };
    auto stA = [&](float4 v) {
        if (ATRANS) {
            int r = tid >> 4, c4 = (tid & 15) << 2;
            As[r][c4] = v.x; As[r][c4 + 1] = v.y; As[r][c4 + 2] = v.z; As[r][c4 + 3] = v.w;
        } else {
            int m = tid >> 2, kq = (tid & 3) << 2;
            As[kq][m] = v.x; As[kq + 1][m] = v.y; As[kq + 2][m] = v.z; As[kq + 3][m] = v.w;
        }
    };
    auto ldB_t = [&](int ko, float4& b0, float4& b1) {
        int r = tid >> 5, c4 = (tid & 31) << 2;
        b0 = *(const float4*)(B + (long)(ko + r) * ldB + n0 + c4);
        b1 = *(const float4*)(B + (long)(ko + r + 8) * ldB + n0 + c4);
    };
    auto stB = [&](float4 b0, float4 b1) {
        int r = tid >> 5, c4 = (tid & 31) << 2;
        *(float4*)&Bs[r][c4] = b0;
        *(float4*)&Bs[r + 8][c4] = b1;
    };

    { float4 a0 = ldA_t(koB); float4 b0, b1; ldB_t(koB, b0, b1);
      stA(a0); stB(b0, b1); }
    __syncthreads();
    for (int ko = koB; ko < koE; ko += BK) {
        bool has = (ko + BK) < koE;
        float4 nA, nB0, nB1;
        if (has) { nA = ldA_t(ko + BK); ldB_t(ko + BK, nB0, nB1); }
#pragma unroll
        for (int kk = 0; kk < BK; ++kk) {
            float4 av = *(const float4*)&As[kk][ty << 2];
            float a_[4] = {av.x, av.y, av.z, av.w};
            float2 b_[4];
#pragma unroll
            for (int p = 0; p < 4; ++p)
                b_[p] = *(const float2*)&Bs[kk][(tx << 1) + (p << 5)];
#pragma unroll
            for (int i = 0; i < 4; ++i) {
                float2 ad = make_float2(a_[i], a_[i]);
#pragma unroll
                for (int p = 0; p < 4; ++p) fma2(acc[i][p], ad, b_[p]);
            }
        }
        __syncthreads();
        if (has) { stA(nA); stB(nB0, nB1); __syncthreads(); }
    }
#pragma unroll
    for (int i = 0; i < 4; ++i) {
        int m = m0 + (ty << 2) + i;
        if (m >= M) continue;
#pragma unroll
        for (int p = 0; p < 4; ++p) {
            int col = n0 + (tx << 1) + (p << 5);
            float2 v = acc[i][p];
            if (ROLE == 0 || ROLE == 2) {
                int chunk = (ROLE == 0) ? 0 : 1;
                long off = (((long)((chunk * 16 + n) * 12 + (col >> 6))) * 128 + m) * 128 +
                           (((col & 63) * 2) ^ ((m & 7) << 4));
                *(uint32_t*)((char*)g_Atil + off) = pkbf(v.x, v.y);
                if (ROLE == 0)
                    *(float2*)&g_ent[((long)(n * cE + m)) * cD + col] = v;
            } else if (ROLE == 1) {
                *(float2*)&g_X[((long)(n * cE + m)) * cS + col] = v;
            } else {
                *(float2*)&Cout[(long)m * cNH + col] = v;
            }
        }
    }
}

// ---- w (256 thr) ----
__device__ void dev_w(int bid) {
    int n = bid >> 7, e = bid & 127;
    int wid = threadIdx.x >> 5, lane = threadIdx.x & 31;
    const float* er = g_ent + ((long)(n * cE + e)) * cD;
    for (int a = wid; a < cA; a += 8) {
        const float* ar = g_argemb + ((long)(n * cA + a)) * cD;
        float acc = 0.f;
        for (int r = lane; r < cD; r += 32) acc += er[r] * ar[r];
        for (int o = 16; o > 0; o >>= 1) acc += __shfl_xor_sync(0xffffffffu, acc, o);
        if (lane == 0)
            g_w[(n * cE + e) * cA + a] = (acc * 0.03608439182435161f - 5.0f) * 0.5f;
    }
}

// ---- atok ----
__device__ void dev_atok(int bid) {
    int n = bid / cA, a = bid % cA;
    int tid = threadIdx.x;
    if (tid >= 192) return;
    int d = tid << 2;
    float4 acc = make_float4(0.f, 0.f, 0.f, 0.f);
    for (int e = 0; e < cE; ++e) {
        float wv = g_w[(n * cE + e) * cA + a];
        float4 v = *(const float4*)&g_ent[((long)(n * cE + e)) * cD + d];
        acc.x += wv * v.x; acc.y += wv * v.y; acc.z += wv * v.z; acc.w += wv * v.w;
    }
    *(float4*)&g_atok[((long)(n * cA + a)) * cD + d] = acc;
}

// ---- epart HMMA (bulk-copy pipeline), 96 blocks ----
constexpr int EP_TILE  = 16384;
constexpr int EP_STG   = 2 * EP_TILE;
constexpr int EP_NST   = 3;
constexpr int EP_SMEM  = 128 + EP_NST * EP_STG;   // 98432
constexpr int EP_ITERS = 24;

__device__ void dev_epart(char* sm, int bid) {
    uint32_t smB = smem_u32(sm);
    int tid = threadIdx.x, lane = tid & 31, wid = tid >> 5;
    int mt = bid & 15, nt = bid >> 4;
    int warpM = (wid & 3) * 32, warpN = (wid >> 2) * 64;

    if (tid == 0)
        for (int s = 0; s < EP_NST; ++s)
            asm volatile("mbarrier.init.shared.b64 [%0], 1;" :: "r"(smB + s * 8) : "memory");
    __syncthreads();

    auto issue = [&](int t, int stg) {
        int chunk = t / 12, kt = t % 12;
        const char* srcA = (const char*)g_Atil +
            ((long)((chunk * 16 + mt) * 12 + kt)) * EP_TILE;
        const char* srcB = (const char*)g_Btil +
            ((long)((chunk * 6 + nt) * 12 + kt)) * EP_TILE;
        uint32_t mbar = smB + stg * 8;
        uint32_t dst  = smB + 128 + stg * EP_STG;
        asm volatile("mbarrier.arrive.expect_tx.shared.b64 _, [%0], %1;"
                     :: "r"(mbar), "r"((uint32_t)EP_STG) : "memory");
        asm volatile("cp.async.bulk.shared::cta.global.mbarrier::complete_tx::bytes "
                     "[%0], [%1], %2, [%3];"
                     :: "r"(dst), "l"(srcA), "r"((uint32_t)EP_TILE), "r"(mbar) : "memory");
        asm volatile("cp.async.bulk.shared::cta.global.mbarrier::complete_tx::bytes "
                     "[%0], [%1], %2, [%3];"
                     :: "r"(dst + EP_TILE), "l"(srcB), "r"((uint32_t)EP_TILE), "r"(mbar) : "memory");
    };
    if (tid == 0) { issue(0, 0); issue(1, 1); issue(2, 2); }

    float acc[2][8][4];
#pragma unroll
    for (int mi = 0; mi < 2; ++mi)
#pragma unroll
        for (int ni = 0; ni < 8; ++ni)
#pragma unroll
            for (int c = 0; c < 4; ++c) acc[mi][ni][c] = 0.f;

    uint32_t ph[EP_NST] = {0, 0, 0};
    for (int t = 0; t < EP_ITERS; ++t) {
        int stg = t % EP_NST;
        mbar_wait(smB + stg * 8, ph[stg]);
        ph[stg] ^= 1;
        uint32_t aS = smB + 128 + stg * EP_STG, bS = aS + EP_TILE;
#pragma unroll
        for (int ks = 0; ks < 64; ks += 16) {
            uint32_t kb = (uint32_t)((ks + (lane & 3) * 2) * 2);
            uint32_t afr[2][4];
#pragma unroll
            for (int mi = 0; mi < 2; ++mi) {
                int row = warpM + mi * 16 + (lane >> 2);
                uint32_t x = (uint32_t)(row & 7) << 4;
                uint32_t p0 = aS + row * 128 + (kb ^ x);
                uint32_t p1 = aS + row * 128 + ((kb + 16) ^ x);
                afr[mi][0] = lds32(p0);
                afr[mi][1] = lds32(p0 + 1024);
                afr[mi][2] = lds32(p1);
                afr[mi][3] = lds32(p1 + 1024);
            }
#pragma unroll
            for (int ni = 0; ni < 8; ++ni) {
                int row = warpN + ni * 8 + (lane >> 2);
                uint32_t x = (uint32_t)(row & 7) << 4;
                uint32_t b0 = lds32(bS + row * 128 + (kb ^ x));
                uint32_t b1 = lds32(bS + row * 128 + ((kb + 16) ^ x));
                mma16816(acc[0][ni], afr[0], b0, b1);
                mma16816(acc[1][ni], afr[1], b0, b1);
            }
        }
        __syncthreads();
        if (t + EP_NST < EP_ITERS && tid == 0) issue(t + EP_NST, stg);
    }
#pragma unroll
    for (int mi = 0; mi < 2; ++mi) {
#pragma unroll
        for (int ni = 0; ni < 8; ++ni) {
            int r = mt * 128 + warpM + mi * 16 + (lane >> 2);
            int c = nt * 128 + warpN + ni * 8 + (lane & 3) * 2;
            *(float2*)&g_Epart[(long)r * cNH + c] =
                make_float2(acc[mi][ni][0], acc[mi][ni][1]);
            *(float2*)&g_Epart[(long)(r + 8) * cNH + c] =
                make_float2(acc[mi][ni][2], acc[mi][ni][3]);
        }
    }
}

// ---- redA: sum early slices ----
__device__ void dev_redA(int bid) {
    int i = bid * 256 + threadIdx.x;
    if (i < SZA) {
        g_ApartE[i] = g_Apart8[i] + g_Apart8[(long)SZA + i] +
                      g_Apart8[2L * SZA + i] + g_Apart8[3L * SZA + i];
        g_Y2[i] = g_Apart8[4L * SZA + i] + g_Apart8[5L * SZA + i];
    }
}

// ---- final (256 thr) ----
__device__ void dev_final(char* sm, int bid,
                          const float* __restrict__ b1, const float* __restrict__ W2,
                          const float* __restrict__ b2, const int* __restrict__ argmap,
                          float* __restrict__ out) {
    float* sEp    = (float*)sm;                 // 768
    float* sw9    = (float*)(sm + 3072);        // 9
    float* sScore = (float*)(sm + 3136);        // 9
    int n = bid >> 7, e = bid & 127;
    int tid = threadIdx.x;
    if (tid < cA) sw9[tid] = g_w[(n * cE + e) * cA + tid];
    __syncthreads();
    for (int r = tid; r < cNH; r += 256) {
        float s = g_Epart[((long)(n * cE + e)) * cNH + r] + b1[r];
#pragma unroll
        for (int a = 0; a < cA; ++a) s += sw9[a] * g_Y2[((long)(n * cA + a)) * cNH + r];
        sEp[r] = s;
    }
    __syncthreads();
    int wid = tid >> 5, lane = tid & 31;
    for (int a = wid; a < cA; a += 8) {
        const float* apE = g_ApartE + ((long)(n * cA + a)) * cNH;
        const float* apL = g_AtokW4 + ((long)(n * cA + a)) * cNH;
        float acc = 0.f;
        for (int r = lane; r < cNH; r += 32) {
            float pre = sEp[r] + apE[r] + apL[r];
            float h = 0.5f * pre * (1.0f + erff(pre * 0.7071067811865476f));
            acc += h * W2[r];
        }
        for (int o = 16; o > 0; o >>= 1) acc += __shfl_xor_sync(0xffffffffu, acc, o);
        if (lane == 0) sScore[a] = acc + b2[0];
    }
    __syncthreads();
    if (tid < cROLES) {
        float v = -1000000.0f;
#pragma unroll
        for (int a = 0; a < cA; ++a)
            if (argmap[n * cA + a] == tid) v = sScore[a];
        out[((long)(n * cE + e)) * cROLES + tid] = v;
    }
}

// ======================= phase kernels ======================================
__global__ void __launch_bounds__(256, 1) k_p1(const float* attn, const float* emb,
                                               const int* idxs, const float* W1) {
    extern __shared__ char sm[];
    int b = blockIdx.x;
    if (b < 2048) dev_t2t(sm, b, attn, idxs);
    else if (b < 2048 + 2192) dev_gather(b - 2048, emb, idxs);
    else dev_convW(sm, b - 4240, W1);
}
__global__ void __launch_bounds__(256, 1) k_p2(const float* em, const float* argw) {
    extern __shared__ char sm[];
    int b = blockIdx.x;
    if (b < 192)      dev_gemm<0>(sm, b & 1, (b >> 1) % 6, b / 12, em, nullptr);
    else if (b < 224) { int i = b - 192; dev_gemm<1>(sm, i & 1, 0, i >> 1, em, nullptr); }
    else              dev_argsmall(sm, b - 224, argw);
}
__global__ void __launch_bounds__(256, 1) k_p3(const float* W1) {
    extern __shared__ char sm[];
    int b = blockIdx.x;
    if (b < 192)      dev_gemm<2>(sm, b & 1, (b >> 1) % 6, b / 12, nullptr, nullptr);
    else if (b < 300) { int i = b - 192; dev_gemm<4>(sm, i % 3, (i / 3) % 6, i / 18, nullptr, W1); }
    else              dev_w(b - 300);
}
__global__ void __launch_bounds__(256, 1) k_p4() {
    extern __shared__ char sm[];
    int b = blockIdx.x;
    if (b < 96) dev_epart(sm, b);
    else        dev_atok(b - 96);
}
__global__ void __launch_bounds__(256, 1) k_p5(const float* W1) {
    extern __shared__ char sm[];
    int b = blockIdx.x;
    if (b < 18) { dev_gemm<5>(sm, b % 3, b / 3, 0, nullptr, W1); }
    else        dev_redA(b - 18);
}
__global__ void __launch_bounds__(256, 1) k_p6(const float* b1, const float* W2,
                                               const float* b2, const int* argmap,
                                               float* out) {
    extern __shared__ char sm[];
    dev_final(sm, blockIdx.x, b1, W2, b2, argmap, out);
}

// ---------------- launch ----------------------------------------------------
extern "C" void kernel_launch(void* const* d_in, const int* in_sizes, int n_in,
                              void* d_out, int out_size) {
    const float* emb  = (const float*)d_in[0];
    const float* attn = (const float*)d_in[1];
    const float* em   = (const float*)d_in[2];
    const float* argw = (const float*)d_in[3];
    const float* W1   = (const float*)d_in[5];
    const float* b1   = (const float*)d_in[6];
    const float* W2   = (const float*)d_in[7];
    const float* b2   = (const float*)d_in[8];
    const int*   idxs = (const int*)d_in[9];
    const int*   amap = (const int*)d_in[10];
    float* out = (float*)d_out;

    cudaFuncSetAttribute(k_p4, cudaFuncAttributeMaxDynamicSharedMemorySize, EP_SMEM);

    k_p1<<<5392, 256, 38912>>>(attn, emb, idxs, W1);
    k_p2<<<240,  256, 28656>>>(em, argw);
    k_p3<<<2348, 256, 12544>>>(W1);
    k_p4<<<240,  256, EP_SMEM>>>();
    k_p5<<<450,  256, 12544>>>(W1);
    k_p6<<<2048, 256, 3200>>>(b1, W2, b2, amap, out);
}

// round 7
// speedup vs baseline: 3.1143x; 1.3566x over previous
#include <cuda_runtime.h>
#include <cuda_bf16.h>
#include <cstdint>

constexpr int cN  = 16, cL = 256, cS = 128, cE = 128, cA = 9;
constexpr int cD  = 768, cNH = 768, cIDXW = 130, cROLES = 24;
constexpr int cM  = cN * cA;            // 144
constexpr int SZA = cM * cNH;           // 110592

// ---------------- scratch ---------------------------------------------------
__device__ float g_sent   [cN * cS * cD];
__device__ float g_argraw [cN * cA * cD];
__device__ float g_argemb [cN * cA * cD];
__device__ float g_u2u    [cN * cA * cD];
__device__ float g_t2t    [cN * cS * cS];
__device__ float g_ent    [cN * cE * cD];
__device__ float g_X      [cN * cE * cS];
__device__ float g_w      [cN * cE * cA];
__device__ float g_Epart  [cN * cE * cNH];
__device__ float g_Apart12[12 * SZA];   // slices 0-7: W1/W5 quarters, 8-11: W2
__device__ float g_ApartE [SZA];
__device__ float g_AtokW4 [SZA];
__device__ float g_Y2     [SZA];
__device__ __nv_bfloat16 g_Atil[2 * cN * cE * cD];   // tiled bf16 {ent, Ah2h}
__device__ __nv_bfloat16 g_Btil[3 * cNH * cD];       // tiled bf16 W {0,3,4}

// ---------------- helpers ---------------------------------------------------
__device__ __forceinline__ void fma2(float2& d, float2 a, float2 b) {
    asm("fma.rn.f32x2 %0, %1, %2, %0;"
        : "+l"(reinterpret_cast<unsigned long long&>(d))
        : "l"(reinterpret_cast<unsigned long long&>(a)),
          "l"(reinterpret_cast<unsigned long long&>(b)));
}
__device__ __forceinline__ uint32_t smem_u32(const void* p) {
    return (uint32_t)__cvta_generic_to_shared(p);
}
__device__ __forceinline__ uint32_t pkbf(float a, float b) {
    __nv_bfloat162 h = __floats2bfloat162_rn(a, b);
    return *reinterpret_cast<uint32_t*>(&h);
}
__device__ __forceinline__ void ldsm4(uint32_t* r, uint32_t addr) {
    asm volatile("ldmatrix.sync.aligned.m8n8.x4.shared.b16 {%0,%1,%2,%3}, [%4];"
        : "=r"(r[0]), "=r"(r[1]), "=r"(r[2]), "=r"(r[3]) : "r"(addr));
}
__device__ __forceinline__ void mma16816(float* c, const uint32_t* a,
                                         uint32_t b0, uint32_t b1) {
    asm volatile(
        "mma.sync.aligned.m16n8k16.row.col.f32.bf16.bf16.f32 "
        "{%0,%1,%2,%3}, {%4,%5,%6,%7}, {%8,%9}, {%0,%1,%2,%3};"
        : "+f"(c[0]), "+f"(c[1]), "+f"(c[2]), "+f"(c[3])
        : "r"(a[0]), "r"(a[1]), "r"(a[2]), "r"(a[3]), "r"(b0), "r"(b1));
}
__device__ __forceinline__ void mbar_wait(uint32_t mbar, uint32_t parity) {
    uint32_t done;
    asm volatile("{\n\t.reg .pred p;\n\t"
        "mbarrier.try_wait.parity.acquire.cta.shared::cta.b64 p, [%1], %2;\n\t"
        "selp.b32 %0, 1, 0, p;\n\t}" : "=r"(done) : "r"(mbar), "r"(parity) : "memory");
    while (!done)
        asm volatile("{\n\t.reg .pred p;\n\t"
            "mbarrier.try_wait.parity.acquire.cta.shared::cta.b64 p, [%1], %2, 0x989680;\n\t"
            "selp.b32 %0, 1, 0, p;\n\t}" : "=r"(done) : "r"(mbar), "r"(parity) : "memory");
}

// ======================= role device functions ==============================

// ---- gather ----
__device__ void dev_gather(int row, const float* __restrict__ emb,
                           const int* __restrict__ idxs) {
    int tid = threadIdx.x;
    if (tid >= 192) return;
    if (row < cN * cS) {
        int n = row >> 7, s = row & 127;
        int src = idxs[n * cIDXW + s];
        ((float4*)(g_sent + (long)row * cD))[tid] =
            ((const float4*)(emb + ((long)n * cL + src) * cD))[tid];
    } else {
        int r = row - cN * cS, n = r / cA, a = r % cA;
        int src = idxs[n * cIDXW + cS] + 1 + a;
        ((float4*)(g_argraw + (long)r * cD))[tid] =
            ((const float4*)(emb + ((long)n * cL + src) * cD))[tid];
    }
}

// ---- t2t ----
__device__ void dev_t2t(char* sm, int bid, const float* __restrict__ attn,
                        const int* __restrict__ idxs) {
    float* rows = (float*)sm;                    // 36*256
    int*   sc   = (int*)(sm + 36864);
    float* r0   = (float*)(sm + 37376);
    float* r1   = (float*)(sm + 37888);
    float* r2   = (float*)(sm + 38400);
    int n = bid >> 7, a = bid & 127;
    int tid = threadIdx.x;
    if (tid < cS) sc[tid] = idxs[n * cIDXW + tid];
    __syncthreads();
    int i = sc[a];
    for (int idx = tid; idx < 36 * 64; idx += 256) {
        int r = idx >> 6, c = idx & 63;
        int l = r / 12, h = r - l * 12;
        long off = ((((long)l * cN + n) * 12 + h) * cL + i) * cL;
        *(float4*)&rows[r * 256 + c * 4] = *(const float4*)(attn + off + c * 4);
    }
    __syncthreads();
    float a0 = 0.f, a1 = 0.f, a2 = 0.f;
    if (tid < cS) {
        int j = sc[tid];
#pragma unroll
        for (int h = 0; h < 12; ++h) {
            a0 += rows[h * 256 + j];
            a1 += rows[(12 + h) * 256 + j];
            a2 += rows[(24 + h) * 256 + j];
        }
        r0[tid] = a0; r1[tid] = a1; r2[tid] = a2;
    }
    __syncthreads();
    for (int st = 64; st > 0; st >>= 1) {
        if (tid < st) { r0[tid] += r0[tid + st]; r1[tid] += r1[tid + st]; r2[tid] += r2[tid + st]; }
        __syncthreads();
    }
    if (tid < cS) {
        float d0 = r0[0] * (1.f / 12.f) + 1e-9f;
        float d1 = r1[0] * (1.f / 12.f) + 1e-9f;
        float d2 = r2[0] * (1.f / 12.f) + 1e-9f;
        g_t2t[((long)(n * cS + a)) * cS + tid] =
            ((a0 * (1.f / 12.f)) / d0 + (a1 * (1.f / 12.f)) / d1 +
             (a2 * (1.f / 12.f)) / d2) * (1.f / 3.f);
    }
}

// ---- convW: W1 blocks {0,3,4} -> tiled swizzled bf16 ----
__device__ void dev_convW(char* sm, int bid, const float* __restrict__ W1) {
    float (*tile)[33] = (float(*)[33])sm;
    int bx = bid % 24, by = (bid / 24) % 24, blk = bid / 576;  // 0,1,2
    int wb = (blk == 0) ? 0 : (blk == 1 ? 3 : 4);
    int tid = threadIdx.x, tx = tid & 31, ty = tid >> 5;
    const float* src = W1 + (long)wb * cD * cNH;
    int k0 = by * 32, n0 = bx * 32;
#pragma unroll
    for (int j = 0; j < 4; ++j)
        tile[ty + j * 8][tx] = src[(long)(k0 + ty + j * 8) * cNH + n0 + tx];
    __syncthreads();
#pragma unroll
    for (int j = 0; j < 4; ++j) {
        int nIdx = n0 + ty + j * 8, kIdx = k0 + tx;
        long off = (((long)(blk * 6 + (nIdx >> 7)) * 12 + (kIdx >> 6)) * 128 +
                    (nIdx & 127)) * 128 +
                   (((kIdx & 63) * 2) ^ ((nIdx & 7) << 4));
        *(__nv_bfloat16*)((char*)g_Btil + off) = __float2bfloat16_rn(tile[tx][ty + j * 8]);
    }
}

// ---- argsmall ----
__device__ void dev_argsmall(char* sm, int n, const float* __restrict__ argw) {
    float* s_ae  = (float*)sm;
    float* s_aw  = (float*)(sm + 27648);
    float* s_dot = (float*)(sm + 27984);
    float* s_a2a = (float*)(sm + 28320);
    int tid = threadIdx.x;
    if (tid < cA * cA) s_aw[tid] = argw[n * cA * cA + tid];
    __syncthreads();
    for (int idx = tid; idx < cA * cD; idx += 256) {
        int a = idx / cD, d = idx % cD;
        float acc = 0.f;
#pragma unroll
        for (int k = 0; k < cA; ++k)
            acc += g_argraw[((long)(n * cA + k)) * cD + d] * s_aw[k * cA + a];
        s_ae[a * cD + d] = acc;
        g_argemb[((long)(n * cA + a)) * cD + d] = acc;
    }
    __syncthreads();
    int wa = tid >> 5, lane = tid & 31;
    for (int p = wa; p < cA * cA; p += 8) {
        int a = p / cA, b = p % cA;
        float acc = 0.f;
        for (int r = lane; r < cD; r += 32) acc += s_ae[a * cD + r] * s_ae[b * cD + r];
        for (int o = 16; o > 0; o >>= 1) acc += __shfl_xor_sync(0xffffffffu, acc, o);
        if (lane == 0) s_dot[p] = acc;
    }
    __syncthreads();
    if (tid < cA) {
        float mx = -1e30f;
        for (int b = 0; b < cA; ++b) mx = fmaxf(mx, s_dot[tid * cA + b]);
        float e[cA], sum = 0.f;
        for (int b = 0; b < cA; ++b) { e[b] = expf(s_dot[tid * cA + b] - mx); sum += e[b]; }
        float inv = 1.f / sum;
        for (int b = 0; b < cA; ++b) s_a2a[tid * cA + b] = e[b] * inv;
    }
    __syncthreads();
    for (int idx = tid; idx < cA * cD; idx += 256) {
        int a = idx / cD, d = idx % cD;
        float acc = 0.f;
#pragma unroll
        for (int b = 0; b < cA; ++b) acc += s_a2a[a * cA + b] * s_ae[b * cD + d];
        g_u2u[((long)(n * cA + a)) * cD + d] = acc;
    }
}

// ---- SIMT GEMM (reg double-buffered) ----
// ROLE 0: ent=em^T@sent (fp32+Atil); 1: X=em^T@t2t; 2: Ah2h=X@sent (Atil only)
// ROLE 4: Apart slices: s=bz in 0..11: chunk=s>>2 {W1,W5,W2}, K-quarter=s&3
template <int ROLE>
__device__ void dev_gemm(char* smraw, int bx, int by, int bz,
                         const float* __restrict__ PA, const float* __restrict__ PB) {
    constexpr bool ATRANS = (ROLE == 0 || ROLE == 1);
    constexpr int BK = 16;
    float (*As)[68]  = reinterpret_cast<float(*)[68]>(smraw);
    float (*Bs)[128] = reinterpret_cast<float(*)[128]>(smraw + BK * 68 * 4);

    const float* A = nullptr; const float* B = nullptr; float* Cout = nullptr;
    int ldA = 0, ldB = 0, M = 0, n = 0, koB = 0, koE = 0;
    if (ROLE == 0) { n = bz; A = PA + (long)n * cS * cE; ldA = cE;
                     B = g_sent + (long)n * cS * cD; ldB = cD; M = cE; koE = cS; }
    if (ROLE == 1) { n = bz; A = PA + (long)n * cS * cE; ldA = cE;
                     B = g_t2t + (long)n * cS * cS; ldB = cS; M = cE; koE = cS; }
    if (ROLE == 2) { n = bz; A = g_X + (long)n * cE * cS; ldA = cS;
                     B = g_sent + (long)n * cS * cD; ldB = cD; M = cE; koE = cS; }
    if (ROLE == 4) { int chunk = bz >> 2, kq = bz & 3;
                     A = (chunk == 1) ? g_u2u : g_argemb; ldA = cD;
                     int wblk = (chunk == 0) ? 1 : (chunk == 1 ? 5 : 2);
                     B = PB + (long)wblk * cD * cNH; ldB = cNH; M = cM;
                     koB = kq * 192; koE = koB + 192;
                     Cout = g_Apart12 + (long)bz * SZA; }
    int m0 = bx * 64, n0 = by * 128;
    int tid = threadIdx.x, tx = tid & 15, ty = tid >> 4;

    float2 acc[4][4];
#pragma unroll
    for (int i = 0; i < 4; ++i)
#pragma unroll
        for (int p = 0; p < 4; ++p) acc[i][p] = make_float2(0.f, 0.f);

    auto ldA_t = [&](int ko) -> float4 {
        if (ATRANS) {
            int r = tid >> 4, c4 = (tid & 15) << 2;
            return *(const float4*)(A + (long)(ko + r) * ldA + m0 + c4);
        } else {
            int m = tid >> 2, kq = (tid & 3) << 2;
            if (m0 + m < M) return *(const float4*)(A + (long)(m0 + m) * ldA + ko + kq);
            return make_float4(0.f, 0.f, 0.f, 0.f);
        }
    };
    auto stA = [&](float4 v) {
        if (ATRANS) {
            int r = tid >> 4, c4 = (tid & 15) << 2;
            As[r][c4] = v.x; As[r][c4 + 1] = v.y; As[r][c4 + 2] = v.z; As[r][c4 + 3] = v.w;
        } else {
            int m = tid >> 2, kq = (tid & 3) << 2;
            As[kq][m] = v.x; As[kq + 1][m] = v.y; As[kq + 2][m] = v.z; As[kq + 3][m] = v.w;
        }
    };
    auto ldB_t = [&](int ko, float4& b0, float4& b1) {
        int r = tid >> 5, c4 = (tid & 31) << 2;
        b0 = *(const float4*)(B + (long)(ko + r) * ldB + n0 + c4);
        b1 = *(const float4*)(B + (long)(ko + r + 8) * ldB + n0 + c4);
    };
    auto stB = [&](float4 b0, float4 b1) {
        int r = tid >> 5, c4 = (tid & 31) << 2;
        *(float4*)&Bs[r][c4] = b0;
        *(float4*)&Bs[r + 8][c4] = b1;
    };

    { float4 a0 = ldA_t(koB); float4 b0, b1; ldB_t(koB, b0, b1);
      stA(a0); stB(b0, b1); }
    __syncthreads();
    for (int ko = koB; ko < koE; ko += BK) {
        bool has = (ko + BK) < koE;
        float4 nA, nB0, nB1;
        if (has) { nA = ldA_t(ko + BK); ldB_t(ko + BK, nB0, nB1); }
#pragma unroll
        for (int kk = 0; kk < BK; ++kk) {
            float4 av = *(const float4*)&As[kk][ty << 2];
            float a_[4] = {av.x, av.y, av.z, av.w};
            float2 b_[4];
#pragma unroll
            for (int p = 0; p < 4; ++p)
                b_[p] = *(const float2*)&Bs[kk][(tx << 1) + (p << 5)];
#pragma unroll
            for (int i = 0; i < 4; ++i) {
                float2 ad = make_float2(a_[i], a_[i]);
#pragma unroll
                for (int p = 0; p < 4; ++p) fma2(acc[i][p], ad, b_[p]);
            }
        }
        __syncthreads();
        if (has) { stA(nA); stB(nB0, nB1); __syncthreads(); }
    }
#pragma unroll
    for (int i = 0; i < 4; ++i) {
        int m = m0 + (ty << 2) + i;
        if (m >= M) continue;
#pragma unroll
        for (int p = 0; p < 4; ++p) {
            int col = n0 + (tx << 1) + (p << 5);
            float2 v = acc[i][p];
            if (ROLE == 0 || ROLE == 2) {
                int chunk = (ROLE == 0) ? 0 : 1;
                long off = (((long)((chunk * 16 + n) * 12 + (col >> 6))) * 128 + m) * 128 +
                           (((col & 63) * 2) ^ ((m & 7) << 4));
                *(uint32_t*)((char*)g_Atil + off) = pkbf(v.x, v.y);
                if (ROLE == 0)
                    *(float2*)&g_ent[((long)(n * cE + m)) * cD + col] = v;
            } else if (ROLE == 1) {
                *(float2*)&g_X[((long)(n * cE + m)) * cS + col] = v;
            } else {
                *(float2*)&Cout[(long)m * cNH + col] = v;
            }
        }
    }
}

// ---- w ----
__device__ void dev_w(int bid) {
    int n = bid >> 7, e = bid & 127;
    int wid = threadIdx.x >> 5, lane = threadIdx.x & 31;
    const float* er = g_ent + ((long)(n * cE + e)) * cD;
    for (int a = wid; a < cA; a += 8) {
        const float* ar = g_argemb + ((long)(n * cA + a)) * cD;
        float acc = 0.f;
        for (int r = lane; r < cD; r += 32) acc += er[r] * ar[r];
        for (int o = 16; o > 0; o >>= 1) acc += __shfl_xor_sync(0xffffffffu, acc, o);
        if (lane == 0)
            g_w[(n * cE + e) * cA + a] = (acc * 0.03608439182435161f - 5.0f) * 0.5f;
    }
}

// ---- epart HMMA (ldmatrix + bulk-copy pipeline) ----
constexpr int EP_TILE  = 16384;
constexpr int EP_STG   = 2 * EP_TILE;
constexpr int EP_NST   = 3;
constexpr int EP_SMEM  = 128 + EP_NST * EP_STG;   // 98432

__device__ void dev_epart(char* sm, int bid) {
    uint32_t smB = smem_u32(sm);
    bool isW4 = bid >= 96;
    int u = isW4 ? bid - 96 : bid;
    int mt = u & 15, nt = u >> 4;                  // 16 x 6
    int iters = isW4 ? 12 : 24;
    int tid = threadIdx.x, lane = tid & 31, wid = tid >> 5;
    int warpM = (wid & 3) * 32, warpN = (wid >> 2) * 64;
    int lrow = lane & 7, lsel = lane >> 3;

    if (tid == 0)
        for (int s = 0; s < EP_NST; ++s)
            asm volatile("mbarrier.init.shared.b64 [%0], 1;" :: "r"(smB + s * 8) : "memory");
    __syncthreads();

    auto issue = [&](int t, int stg) {
        int achunk = isW4 ? 0 : t / 12;
        int bblk   = isW4 ? 2 : t / 12;
        int kt = t % 12;
        const char* srcA = (const char*)g_Atil +
            ((long)((achunk * 16 + mt) * 12 + kt)) * EP_TILE;
        const char* srcB = (const char*)g_Btil +
            ((long)((bblk * 6 + nt) * 12 + kt)) * EP_TILE;
        uint32_t mbar = smB + stg * 8;
        uint32_t dst  = smB + 128 + stg * EP_STG;
        asm volatile("mbarrier.arrive.expect_tx.shared.b64 _, [%0], %1;"
                     :: "r"(mbar), "r"((uint32_t)EP_STG) : "memory");
        asm volatile("cp.async.bulk.shared::cta.global.mbarrier::complete_tx::bytes "
                     "[%0], [%1], %2, [%3];"
                     :: "r"(dst), "l"(srcA), "r"((uint32_t)EP_TILE), "r"(mbar) : "memory");
        asm volatile("cp.async.bulk.shared::cta.global.mbarrier::complete_tx::bytes "
                     "[%0], [%1], %2, [%3];"
                     :: "r"(dst + EP_TILE), "l"(srcB), "r"((uint32_t)EP_TILE), "r"(mbar) : "memory");
    };
    if (tid == 0) { issue(0, 0); issue(1, 1); issue(2, 2); }

    float acc[2][8][4];
#pragma unroll
    for (int mi = 0; mi < 2; ++mi)
#pragma unroll
        for (int ni = 0; ni < 8; ++ni)
#pragma unroll
            for (int c = 0; c < 4; ++c) acc[mi][ni][c] = 0.f;

    uint32_t ph[EP_NST] = {0, 0, 0};
    for (int t = 0; t < iters; ++t) {
        int stg = t % EP_NST;
        mbar_wait(smB + stg * 8, ph[stg]);
        ph[stg] ^= 1;
        uint32_t aS = smB + 128 + stg * EP_STG, bS = aS + EP_TILE;
#pragma unroll
        for (int ks = 0; ks < 64; ks += 16) {
            uint32_t kbyte = (uint32_t)(ks * 2 + ((lsel >> 1) << 4));
            uint32_t afr[2][4], bfr[4][4];
#pragma unroll
            for (int mi = 0; mi < 2; ++mi) {
                int row = warpM + mi * 16 + lrow + ((lsel & 1) << 3);
                ldsm4(afr[mi], aS + row * 128 + (kbyte ^ ((row & 7) << 4)));
            }
#pragma unroll
            for (int g = 0; g < 4; ++g) {
                int row = warpN + g * 16 + lrow + ((lsel & 1) << 3);
                ldsm4(bfr[g], bS + row * 128 + (kbyte ^ ((row & 7) << 4)));
            }
#pragma unroll
            for (int g = 0; g < 4; ++g) {
                mma16816(acc[0][2 * g],     afr[0], bfr[g][0], bfr[g][2]);
                mma16816(acc[0][2 * g + 1], afr[0], bfr[g][1], bfr[g][3]);
                mma16816(acc[1][2 * g],     afr[1], bfr[g][0], bfr[g][2]);
                mma16816(acc[1][2 * g + 1], afr[1], bfr[g][1], bfr[g][3]);
            }
        }
        __syncthreads();
        if (t + EP_NST < iters && tid == 0) issue(t + EP_NST, stg);
    }

    if (!isW4) {
#pragma unroll
        for (int mi = 0; mi < 2; ++mi)
#pragma unroll
            for (int ni = 0; ni < 8; ++ni) {
                int r = mt * 128 + warpM + mi * 16 + (lane >> 2);
                int c = nt * 128 + warpN + ni * 8 + (lane & 3) * 2;
                *(float2*)&g_Epart[(long)r * cNH + c] =
                    make_float2(acc[mi][ni][0], acc[mi][ni][1]);
                *(float2*)&g_Epart[(long)(r + 8) * cNH + c] =
                    make_float2(acc[mi][ni][2], acc[mi][ni][3]);
            }
    } else {
        // EntW4 tile -> smem, then AtokW4[n, a, cols] = sum_e w[n,e,a]*tile[e][col]
        __syncthreads();
        float* tile = (float*)(sm + 128);            // [128][132]
        float* sw   = tile + 128 * 132;              // [128][9]
#pragma unroll
        for (int mi = 0; mi < 2; ++mi)
#pragma unroll
            for (int ni = 0; ni < 8; ++ni) {
                int r = warpM + mi * 16 + (lane >> 2);
                int c = warpN + ni * 8 + (lane & 3) * 2;
                *(float2*)&tile[r * 132 + c] =
                    make_float2(acc[mi][ni][0], acc[mi][ni][1]);
                *(float2*)&tile[(r + 8) * 132 + c] =
                    make_float2(acc[mi][ni][2], acc[mi][ni][3]);
            }
        if (tid < 128)
#pragma unroll
            for (int a = 0; a < cA; ++a)
                sw[tid * 9 + a] = g_w[(mt * cE + tid) * cA + a];
        __syncthreads();
        int col = tid & 127, h = tid >> 7;
        for (int a = h; a < cA; a += 2) {
            float s = 0.f;
#pragma unroll 8
            for (int e = 0; e < cE; ++e) s += sw[e * 9 + a] * tile[e * 132 + col];
            g_AtokW4[((long)(mt * cA + a)) * cNH + nt * 128 + col] = s;
        }
    }
}

// ---- redA (float4) ----
__device__ void dev_redA(int bid) {
    int i = (bid * 256 + threadIdx.x) * 4;
    if (i < SZA) {
        float4 sE = make_float4(0.f, 0.f, 0.f, 0.f);
        float4 sY = make_float4(0.f, 0.f, 0.f, 0.f);
#pragma unroll
        for (int k = 0; k < 8; ++k) {
            float4 v = *(const float4*)&g_Apart12[(long)k * SZA + i];
            sE.x += v.x; sE.y += v.y; sE.z += v.z; sE.w += v.w;
        }
#pragma unroll
        for (int k = 8; k < 12; ++k) {
            float4 v = *(const float4*)&g_Apart12[(long)k * SZA + i];
            sY.x += v.x; sY.y += v.y; sY.z += v.z; sY.w += v.w;
        }
        *(float4*)&g_ApartE[i] = sE;
        *(float4*)&g_Y2[i] = sY;
    }
}

// ---- final ----
__device__ void dev_final(char* sm, int bid,
                          const float* __restrict__ b1, const float* __restrict__ W2,
                          const float* __restrict__ b2, const int* __restrict__ argmap,
                          float* __restrict__ out) {
    float* sEp    = (float*)sm;
    float* sw9    = (float*)(sm + 3072);
    float* sScore = (float*)(sm + 3136);
    int n = bid >> 7, e = bid & 127;
    int tid = threadIdx.x;
    if (tid < cA) sw9[tid] = g_w[(n * cE + e) * cA + tid];
    __syncthreads();
    for (int r = tid; r < cNH; r += 256) {
        float s = g_Epart[((long)(n * cE + e)) * cNH + r] + b1[r];
#pragma unroll
        for (int a = 0; a < cA; ++a) s += sw9[a] * g_Y2[((long)(n * cA + a)) * cNH + r];
        sEp[r] = s;
    }
    __syncthreads();
    int wid = tid >> 5, lane = tid & 31;
    for (int a = wid; a < cA; a += 8) {
        const float* apE = g_ApartE + ((long)(n * cA + a)) * cNH;
        const float* apL = g_AtokW4 + ((long)(n * cA + a)) * cNH;
        float acc = 0.f;
        for (int r = lane; r < cNH; r += 32) {
            float pre = sEp[r] + apE[r] + apL[r];
            float hv = 0.5f * pre * (1.0f + erff(pre * 0.7071067811865476f));
            acc += hv * W2[r];
        }
        for (int o = 16; o > 0; o >>= 1) acc += __shfl_xor_sync(0xffffffffu, acc, o);
        if (lane == 0) sScore[a] = acc + b2[0];
    }
    __syncthreads();
    if (tid < cROLES) {
        float v = -1000000.0f;
#pragma unroll
        for (int a = 0; a < cA; ++a)
            if (argmap[n * cA + a] == tid) v = sScore[a];
        out[((long)(n * cE + e)) * cROLES + tid] = v;
    }
}

// ======================= phase kernels ======================================
__global__ void __launch_bounds__(256, 1) k_p1(const float* attn, const float* emb,
                                               const int* idxs, const float* W1) {
    extern __shared__ char sm[];
    int b = blockIdx.x;
    if (b < 2048) dev_t2t(sm, b, attn, idxs);
    else if (b < 4240) dev_gather(b - 2048, emb, idxs);
    else dev_convW(sm, b - 4240, W1);
}
__global__ void __launch_bounds__(256, 1) k_p2(const float* em, const float* argw) {
    extern __shared__ char sm[];
    int b = blockIdx.x;
    if (b < 192)      dev_gemm<0>(sm, b & 1, (b >> 1) % 6, b / 12, em, nullptr);
    else if (b < 224) { int i = b - 192; dev_gemm<1>(sm, i & 1, 0, i >> 1, em, nullptr); }
    else              dev_argsmall(sm, b - 224, argw);
}
__global__ void __launch_bounds__(256, 1) k_p3(const float* W1) {
    extern __shared__ char sm[];
    int b = blockIdx.x;
    if (b < 216)      dev_gemm<4>(sm, b % 3, (b / 3) % 6, b / 18, nullptr, W1);
    else if (b < 408) { int i = b - 216; dev_gemm<2>(sm, i & 1, (i >> 1) % 6, i / 12, nullptr, nullptr); }
    else              dev_w(b - 408);
}
__global__ void __launch_bounds__(256, 1) k_p4() {
    extern __shared__ char sm[];
    int b = blockIdx.x;
    if (b < 192) dev_epart(sm, b);
    else         dev_redA(b - 192);
}
__global__ void __launch_bounds__(256, 1) k_p5(const float* b1, const float* W2,
                                               const float* b2, const int* argmap,
                                               float* out) {
    extern __shared__ char sm[];
    dev_final(sm, blockIdx.x, b1, W2, b2, argmap, out);
}

// ---------------- launch ----------------------------------------------------
extern "C" void kernel_launch(void* const* d_in, const int* in_sizes, int n_in,
                              void* d_out, int out_size) {
    const float* emb  = (const float*)d_in[0];
    const float* attn = (const float*)d_in[1];
    const float* em   = (const float*)d_in[2];
    const float* argw = (const float*)d_in[3];
    const float* W1   = (const float*)d_in[5];
    const float* b1   = (const float*)d_in[6];
    const float* W2   = (const float*)d_in[7];
    const float* b2   = (const float*)d_in[8];
    const int*   idxs = (const int*)d_in[9];
    const int*   amap = (const int*)d_in[10];
    float* out = (float*)d_out;

    cudaFuncSetAttribute(k_p4, cudaFuncAttributeMaxDynamicSharedMemorySize, EP_SMEM);

    k_p1<<<5968, 256, 38912>>>(attn, emb, idxs, W1);
    k_p2<<<240,  256, 28656>>>(em, argw);
    k_p3<<<2456, 256, 12544>>>(W1);
    k_p4<<<300,  256, EP_SMEM>>>();
    k_p5<<<2048, 256, 3200>>>(b1, W2, b2, amap, out);
}